// round 9
// baseline (speedup 1.0000x reference)
#include <cuda_runtime.h>
#include <cuda_bf16.h>
#include <cstdint>
#include <math.h>

// ---------------------------------------------------------------------------
// Problem constants
// ---------------------------------------------------------------------------
#define NB 8
#define SQ 1024
#define SK 1024
#define DD 1024
#define NH 8
#define DH 128
#define HB (NH*NB)              // 64
#define XSIZE (NB*SQ*DD)        // 8388608
#define NEGV (-4294967295.0f)
#define SCALE 0.0883883476483184405f

// mma GEMM smem: per buffer operand slots, each 128 rows x 32 bf16,
// row stride 80B (64B data + 16B skew). 3-stage pipeline.
#define ROWB 80
#define OP_BYTES (128*ROWB)       // 10240
#define OFF_AL (1*OP_BYTES)
#define OFF_BL (3*OP_BYTES)
#define BUF_BYTES (4*OP_BYTES)    // 40960  (3-term: Ah,Al,Bh,Bl)
#define BUF1_BYTES (2*OP_BYTES)   // 20480  (1-term: Ah,Bh)
#define SMEM_TOT (3*BUF_BYTES)    // 122880
#define SMEM1_TOT (3*BUF1_BYTES)  // 61440

// attn_fused smem layout
#define ROWQ 272                  // 256B data + 16B skew
#define S_PITCH 1032              // fp32 words per S row (skewed)
#define SM_Q (32*S_PITCH*4)       // 132096: Q region starts after S
#define B_HL (64*ROWQ)            // 17408
#define B_BUF (2*B_HL)            // 34816
#define SM_B (SM_Q + 2*32*ROWQ)   // 149504
#define SMEM_ATTN (SM_B + 2*B_BUF) // 219136
// phase-2 reuse: Ph (bf16 P) over dead Q/K-buffer space; V tiles over dead S
#define PH_PITCH 2064             // 2048B data + 16B skew (rows hit distinct banks)
#define SM_PH SM_Q                // 132096 .. 132096+32*2064 = 198144
#define VROWB 144                 // 128B data + 16B skew
#define VBUF_BYTES (128*VROWB)    // 18432
#define SM_V0 (SM_PH + 32*PH_PITCH) // 198144 .. 216576  (spare region for tile 0)

// ---------------------------------------------------------------------------
// Scratch (device globals — referenced ONLY from device code)
// ---------------------------------------------------------------------------
__device__ __nv_bfloat16 g_memh[NB*SK*DD], g_meml[NB*SK*DD];
__device__ __nv_bfloat16 g_dech[NB*SQ*DD], g_decl[NB*SQ*DD];
__device__ __nv_bfloat16 g_Wkt_h[DD*DD], g_Wkt_l[DD*DD];
__device__ __nv_bfloat16 g_Wvt_h[DD*DD];
__device__ __nv_bfloat16 g_Wqt_h[DD*DD], g_Wqt_l[DD*DD];
__device__ __nv_bfloat16 g_Wft_h[DD*2*DD], g_Wft_l[DD*2*DD];
__device__ __nv_bfloat16 g_Kh[HB*SK*DH], g_Kl[HB*SK*DH];
__device__ __nv_bfloat16 g_Qh[HB*SQ*DH], g_Ql[HB*SQ*DH];
__device__ float         g_V[HB*SK*DH];
__device__ __nv_bfloat16 g_Vth[HB*DH*SK];
__device__ __nv_bfloat16 g_Oh[NB*SQ*DD];
__device__ float         g_X[NB*SQ*DD];
__device__ int           g_maskmode;

// ---------------------------------------------------------------------------
// Helpers
// ---------------------------------------------------------------------------
__device__ __forceinline__ uint32_t smem_to_u32(const void* p) {
    uint32_t a;
    asm("{ .reg .u64 t; cvta.to.shared.u64 t, %1; cvt.u32.u64 %0, t; }" : "=r"(a) : "l"(p));
    return a;
}

__device__ __forceinline__ void cp16(uint32_t dst, const void* src) {
    asm volatile("cp.async.cg.shared.global [%0], [%1], 16;" :: "r"(dst), "l"(src));
}
#define CP_COMMIT() asm volatile("cp.async.commit_group;" ::: "memory")
#define CP_WAIT(n)  asm volatile("cp.async.wait_group %0;" :: "n"(n) : "memory")

__device__ __forceinline__ void ldm_x4(uint32_t* r, uint32_t addr) {
    asm volatile("ldmatrix.sync.aligned.m8n8.x4.shared.b16 {%0,%1,%2,%3}, [%4];"
        : "=r"(r[0]), "=r"(r[1]), "=r"(r[2]), "=r"(r[3]) : "r"(addr));
}

__device__ __forceinline__ void mma16816(float* d, const uint32_t* a, const uint32_t* b) {
    asm volatile("mma.sync.aligned.m16n8k16.row.col.f32.bf16.bf16.f32 "
        "{%0,%1,%2,%3}, {%4,%5,%6,%7}, {%8,%9}, {%0,%1,%2,%3};"
        : "+f"(d[0]), "+f"(d[1]), "+f"(d[2]), "+f"(d[3])
        : "r"(a[0]), "r"(a[1]), "r"(a[2]), "r"(a[3]), "r"(b[0]), "r"(b[1]));
}

__device__ __forceinline__ void split_hilo(float v, __nv_bfloat16& h, __nv_bfloat16& l) {
    h = __float2bfloat16(v);
    l = __float2bfloat16(v - __bfloat162float(h));
}
__device__ __forceinline__ uint32_t pack2h(float v0, float v1) {
    __nv_bfloat16 h0, l0, h1, l1;
    split_hilo(v0, h0, l0); split_hilo(v1, h1, l1);
    __nv_bfloat162 p = __halves2bfloat162(h0, h1);
    return *reinterpret_cast<uint32_t*>(&p);
}
__device__ __forceinline__ uint32_t pack2l(float v0, float v1) {
    __nv_bfloat16 h0, l0, h1, l1;
    split_hilo(v0, h0, l0); split_hilo(v1, h1, l1);
    __nv_bfloat162 p = __halves2bfloat162(l0, l1);
    return *reinterpret_cast<uint32_t*>(&p);
}

// ---------------------------------------------------------------------------
// mma GEMM building blocks. TERMS=3: hi/lo split; TERMS=1: single bf16.
// ---------------------------------------------------------------------------
template<int TERMS>
__device__ __forceinline__ void load_chunk_t(
    uint32_t sbuf,
    const __nv_bfloat16* __restrict__ Ah, const __nv_bfloat16* __restrict__ Al,
    const __nv_bfloat16* __restrict__ Bh, const __nv_bfloat16* __restrict__ Bl,
    int lda, int ldb, int tid)
{
    constexpr uint32_t OFFB = (TERMS == 3) ? (uint32_t)(2*OP_BYTES) : (uint32_t)OP_BYTES;
#pragma unroll
    for (int i = tid; i < 512; i += 256) {
        int row = i >> 2, ch = i & 3;
        uint32_t d = sbuf + row*ROWB + ch*16;
        size_t ao = (size_t)row * lda * 2 + ch*16;
        size_t bo = (size_t)row * ldb * 2 + ch*16;
        cp16(d,        (const char*)Ah + ao);
        cp16(d + OFFB, (const char*)Bh + bo);
        if (TERMS == 3) {
            cp16(d + OFF_AL, (const char*)Al + ao);
            cp16(d + OFF_BL, (const char*)Bl + bo);
        }
    }
}

template<int TERMS>
__device__ __forceinline__ void compute_chunk_t(uint32_t sbuf, int lane, int m0, int n0,
                                                float acc[2][8][4])
{
    constexpr uint32_t OFFB = (TERMS == 3) ? (uint32_t)(2*OP_BYTES) : (uint32_t)OP_BYTES;
#pragma unroll
    for (int kk = 0; kk < 2; kk++) {
        uint32_t ah[2][4], al[2][4];
        int arow = m0 + (lane & 15);
        uint32_t abase = sbuf + kk*32 + ((lane >> 4) & 1)*16;
        ldm_x4(ah[0], abase + arow*ROWB);
        ldm_x4(ah[1], abase + (arow + 16)*ROWB);
        if (TERMS == 3) {
            ldm_x4(al[0], abase + OFF_AL + arow*ROWB);
            ldm_x4(al[1], abase + OFF_AL + (arow + 16)*ROWB);
        }

        uint32_t bh[4][4], bl[4][4];
        int brow = n0 + ((lane >> 4) << 3) + (lane & 7);
        uint32_t bko = ((lane >> 3) & 1) * 16 + kk*32;
#pragma unroll
        for (int nb = 0; nb < 4; nb++) {
            ldm_x4(bh[nb], sbuf + OFFB + (brow + nb*16)*ROWB + bko);
            if (TERMS == 3)
                ldm_x4(bl[nb], sbuf + OFF_BL + (brow + nb*16)*ROWB + bko);
        }
#pragma unroll
        for (int mi = 0; mi < 2; mi++)
#pragma unroll
            for (int ni = 0; ni < 8; ni++) {
                const uint32_t* BH = &bh[ni >> 1][(ni & 1) * 2];
                mma16816(acc[mi][ni], ah[mi], BH);
                if (TERMS == 3) {
                    const uint32_t* BL = &bl[ni >> 1][(ni & 1) * 2];
                    mma16816(acc[mi][ni], al[mi], BH);
                    mma16816(acc[mi][ni], ah[mi], BL);
                }
            }
    }
}

#define ACC_ZERO() do { \
    _Pragma("unroll") for (int _i = 0; _i < 2; _i++) \
    _Pragma("unroll") for (int _j = 0; _j < 8; _j++) \
    _Pragma("unroll") for (int _k = 0; _k < 4; _k++) acc[_i][_j][_k] = 0.f; \
} while (0)

// 3-stage pipeline driver
#define PIPELINE3(KC, BUFSZ, LOADC, COMPUTEC) do { \
    { LOADC(0, sb + 0*(BUFSZ)); } CP_COMMIT(); \
    { LOADC(1, sb + 1*(BUFSZ)); } CP_COMMIT(); \
    for (int c = 0; c < (KC); c++) { \
        if (c + 2 < (KC)) { LOADC((c + 2), sb + ((c + 2) % 3)*(BUFSZ)); } \
        CP_COMMIT(); \
        CP_WAIT(2); \
        __syncthreads(); \
        { COMPUTEC(c, sb + (c % 3)*(BUFSZ)); } \
        __syncthreads(); \
    } \
} while (0)

// ---------------------------------------------------------------------------
// Mask dtype detection
// ---------------------------------------------------------------------------
__global__ void detect_mask_kernel(const void* __restrict__ mask) {
    int t = threadIdx.x;
    const int* pi = (const int*)mask;
    const float* pf = (const float*)mask;
    bool oki = true, okf = true;
    for (int i = t; i < 256; i += 32) {
        int v = pi[i];
        oki = oki && (v == 0 || v == 1);
        float f = pf[i];
        okf = okf && (f == 0.0f || f == 1.0f);
    }
    oki = __all_sync(0xFFFFFFFFu, oki);
    okf = __all_sync(0xFFFFFFFFu, okf);
    if (t == 0) g_maskmode = oki ? 0 : (okf ? 1 : 2);
}

// ---------------------------------------------------------------------------
// fp32 -> bf16 hi/lo. which=0 -> g_mem*, which=1 -> g_dec*
// ---------------------------------------------------------------------------
__global__ void conv_hilo_kernel(const float* __restrict__ src, int which, int n4) {
    __nv_bfloat16* __restrict__ dh = which ? g_dech : g_memh;
    __nv_bfloat16* __restrict__ dl = which ? g_decl : g_meml;
    int idx = blockIdx.x * blockDim.x + threadIdx.x;
    if (idx >= n4) return;
    float4 v = ((const float4*)src)[idx];
    uint2 hw, lw;
    hw.x = pack2h(v.x, v.y); hw.y = pack2h(v.z, v.w);
    lw.x = pack2l(v.x, v.y); lw.y = pack2l(v.z, v.w);
    ((uint2*)dh)[idx] = hw;
    ((uint2*)dl)[idx] = lw;
}

// ---------------------------------------------------------------------------
// W [K][N] fp32 -> Wt [N][K] bf16 hi/lo. which: 0=Wk 1=Wv(hi only) 2=Wq 3=Wf
// ---------------------------------------------------------------------------
__global__ void convT_kernel(const float* __restrict__ src, int which, int K, int N) {
    __nv_bfloat16 *dh, *dl;
    if (which == 0)      { dh = g_Wkt_h; dl = g_Wkt_l; }
    else if (which == 1) { dh = g_Wvt_h; dl = nullptr; }
    else if (which == 2) { dh = g_Wqt_h; dl = g_Wqt_l; }
    else                 { dh = g_Wft_h; dl = g_Wft_l; }

    __shared__ float t[32][33];
    int n0 = blockIdx.x * 32, k0 = blockIdx.y * 32;
    int tx = threadIdx.x;
    for (int i = threadIdx.y; i < 32; i += 8)
        t[i][tx] = src[(size_t)(k0 + i) * N + n0 + tx];
    __syncthreads();
    for (int i = threadIdx.y; i < 32; i += 8) {
        float v = t[tx][i];
        __nv_bfloat16 h, l;
        split_hilo(v, h, l);
        size_t o = (size_t)(n0 + i) * K + k0 + tx;
        dh[o] = h;
        if (dl) dl[o] = l;
    }
}

// ---------------------------------------------------------------------------
// V [hb][1024][128] fp32 -> Vt [hb][128][1024] bf16 (hi only)
// ---------------------------------------------------------------------------
__global__ void transposeV_kernel() {
    __shared__ float t[32][33];
    int hb = blockIdx.z;
    int d0 = blockIdx.x * 32, s0 = blockIdx.y * 32;
    int tx = threadIdx.x;
    const float* src = g_V + (size_t)hb * SK * DH;
    for (int i = threadIdx.y; i < 32; i += 8)
        t[i][tx] = src[(size_t)(s0 + i) * 128 + d0 + tx];
    __syncthreads();
    for (int i = threadIdx.y; i < 32; i += 8) {
        size_t o = (size_t)hb * DH * SK + (size_t)(d0 + i) * 1024 + s0 + tx;
        g_Vth[o] = __float2bfloat16(t[tx][i]);
    }
}

// ---------------------------------------------------------------------------
// Projection GEMM K/Q (HMMA, 3-term): z=0 K, z=1 Q. Head-split bf16 hi/lo out.
// ---------------------------------------------------------------------------
__global__ __launch_bounds__(256, 1) void projKQ_mma_kernel() {
    extern __shared__ char smem[];
    uint32_t sb = smem_to_u32(smem);
    int tid = threadIdx.x, lane = tid & 31, w = tid >> 5;
    int m0 = (w & 3) * 32, n0 = (w >> 2) * 64;
    int bx = blockIdx.x, by = blockIdx.y, z = blockIdx.z;

    const __nv_bfloat16* Ah = ((z == 1) ? g_dech : g_memh) + (size_t)by * 128 * 1024;
    const __nv_bfloat16* Al = ((z == 1) ? g_decl : g_meml) + (size_t)by * 128 * 1024;
    const __nv_bfloat16* Bh = ((z == 0) ? g_Wkt_h : g_Wqt_h) + (size_t)bx * 128 * 1024;
    const __nv_bfloat16* Bl = ((z == 0) ? g_Wkt_l : g_Wqt_l) + (size_t)bx * 128 * 1024;

    float acc[2][8][4];
    ACC_ZERO();

#define LOADC(cc, buf) load_chunk_t<3>((buf), Ah + (cc)*32, Al + (cc)*32, Bh + (cc)*32, Bl + (cc)*32, 1024, 1024, tid)
#define COMPUTEC(cc, buf) compute_chunk_t<3>((buf), lane, m0, n0, acc)
    PIPELINE3(32, BUF_BYTES, LOADC, COMPUTEC);
#undef LOADC
#undef COMPUTEC

#pragma unroll
    for (int mi = 0; mi < 2; mi++)
#pragma unroll
        for (int ni = 0; ni < 8; ni++) {
            int cc = n0 + ni * 8 + (lane & 3) * 2;
#pragma unroll
            for (int half = 0; half < 2; half++) {
                int rr = by * 128 + m0 + mi * 16 + (lane >> 2) + half * 8;
                float d0 = acc[mi][ni][half * 2], d1 = acc[mi][ni][half * 2 + 1];
                int bb = rr >> 10, ss = rr & 1023;
                size_t base = (((size_t)(bx * 8 + bb)) * 1024 + ss) * 128 + cc;
                __nv_bfloat16* oh = (z == 0) ? g_Kh : g_Qh;
                __nv_bfloat16* ol = (z == 0) ? g_Kl : g_Ql;
                *(uint32_t*)(oh + base) = pack2h(d0, d1);
                *(uint32_t*)(ol + base) = pack2l(d0, d1);
            }
        }
}

// ---------------------------------------------------------------------------
// Projection GEMM V (HMMA, 1-term, compact smem): fp32 head-split out
// ---------------------------------------------------------------------------
__global__ __launch_bounds__(256, 2) void projV_mma_kernel() {
    extern __shared__ char smem[];
    uint32_t sb = smem_to_u32(smem);
    int tid = threadIdx.x, lane = tid & 31, w = tid >> 5;
    int m0 = (w & 3) * 32, n0 = (w >> 2) * 64;
    int bx = blockIdx.x, by = blockIdx.y;

    const __nv_bfloat16* Ah = g_memh + (size_t)by * 128 * 1024;
    const __nv_bfloat16* Bh = g_Wvt_h + (size_t)bx * 128 * 1024;

    float acc[2][8][4];
    ACC_ZERO();

#define LOADC(cc, buf) load_chunk_t<1>((buf), Ah + (cc)*32, nullptr, Bh + (cc)*32, nullptr, 1024, 1024, tid)
#define COMPUTEC(cc, buf) compute_chunk_t<1>((buf), lane, m0, n0, acc)
    PIPELINE3(32, BUF1_BYTES, LOADC, COMPUTEC);
#undef LOADC
#undef COMPUTEC

#pragma unroll
    for (int mi = 0; mi < 2; mi++)
#pragma unroll
        for (int ni = 0; ni < 8; ni++) {
            int cc = n0 + ni * 8 + (lane & 3) * 2;
#pragma unroll
            for (int half = 0; half < 2; half++) {
                int rr = by * 128 + m0 + mi * 16 + (lane >> 2) + half * 8;
                float d0 = acc[mi][ni][half * 2], d1 = acc[mi][ni][half * 2 + 1];
                int bb = rr >> 10, ss = rr & 1023;
                size_t base = (((size_t)(bx * 8 + bb)) * 1024 + ss) * 128 + cc;
                *(float2*)(g_V + base) = make_float2(d0, d1);
            }
        }
}

// ---------------------------------------------------------------------------
// FUSED scores+softmax+PV: one CTA = 32 query rows x 1024 keys for one hb.
// S in smem; softmax writes P fp32 (attns output) + Ph bf16 to smem;
// PV phase streams Vt tiles and writes O (bf16) directly.
// ---------------------------------------------------------------------------
__global__ __launch_bounds__(256, 1) void attn_fused_kernel(
    float* __restrict__ attn, const float* __restrict__ qmask,
    const void* __restrict__ mask)
{
    extern __shared__ char smem[];
    uint32_t sb = smem_to_u32(smem);
    float* Ss = (float*)smem;
    int tid = threadIdx.x, lane = tid & 31, w = tid >> 5;
    const int wm = w >> 2;      // 0..1 -> m16 slice
    const int wn = w & 3;       // 0..3 -> n16 slice within 64-key tile
    int blk = blockIdx.x;       // 0..31 row block
    int y = blockIdx.y;         // 0..63 ; b-major for mask L2 reuse
    int h = y & 7, b = y >> 3;
    int hb = h * 8 + b;
    int q0 = blk * 32;

    const char* Qh = (const char*)(g_Qh + ((size_t)hb * 1024 + q0) * 128);
    const char* Ql = (const char*)(g_Ql + ((size_t)hb * 1024 + q0) * 128);
    const char* Kh = (const char*)(g_Kh + (size_t)hb * 1024 * 128);
    const char* Kl = (const char*)(g_Kl + (size_t)hb * 1024 * 128);
    const char* Vt = (const char*)(g_Vth + (size_t)hb * DH * SK);

    // ---- load Q (32 rows x 256B, hi+lo) ----
#pragma unroll
    for (int i = tid; i < 512; i += 256) {
        int row = i >> 4, ch = i & 15;
        uint32_t d = sb + SM_Q + row * ROWQ + ch * 16;
        size_t o = (size_t)row * 256 + ch * 16;
        cp16(d, Qh + o);
        cp16(d + 32 * ROWQ, Ql + o);
    }
    CP_COMMIT();

    // ---- preload K tiles 0,1 (64 keys x 256B, hi+lo each) ----
#pragma unroll
    for (int t = 0; t < 2; t++) {
        uint32_t bbuf = sb + SM_B + t * B_BUF;
#pragma unroll
        for (int i = tid; i < 1024; i += 256) {
            int row = i >> 4, ch = i & 15;
            uint32_t d = bbuf + row * ROWQ + ch * 16;
            size_t o = (size_t)t * 64 * 256 + (size_t)row * 256 + ch * 16;
            cp16(d, Kh + o);
            cp16(d + B_HL, Kl + o);
        }
        CP_COMMIT();
    }

    // ---- Q ready: hoist A fragments for all 8 kk steps ----
    CP_WAIT(2);
    __syncthreads();
    uint32_t ah_reg[8][4], al_reg[8][4];
    {
        uint32_t abase = sb + SM_Q + (uint32_t)(wm * 16 + (lane & 15)) * ROWQ
                         + ((lane >> 4) & 1) * 16;
#pragma unroll
        for (int kk = 0; kk < 8; kk++) {
            ldm_x4(ah_reg[kk], abase + kk * 32);
            ldm_x4(al_reg[kk], abase + 32 * ROWQ + kk * 32);
        }
    }

    // ---- stream 16 K tiles of 64 keys, double-buffered ----
    const int gid = lane >> 2, tig = lane & 3;
    for (int t = 0; t < 16; t++) {
        CP_WAIT(1);
        __syncthreads();
        uint32_t bbuf = sb + SM_B + (t & 1) * B_BUF;
        float acc[2][4];
#pragma unroll
        for (int ni = 0; ni < 2; ni++)
#pragma unroll
            for (int k = 0; k < 4; k++) acc[ni][k] = 0.f;

        uint32_t bbase = bbuf + (uint32_t)(wn * 16 + ((lane >> 4) << 3) + (lane & 7)) * ROWQ
                         + ((lane >> 3) & 1) * 16;
#pragma unroll
        for (int kk = 0; kk < 8; kk++) {
            uint32_t bh[4], bl[4];
            ldm_x4(bh, bbase + kk * 32);
            ldm_x4(bl, bbase + B_HL + kk * 32);
#pragma unroll
            for (int ni = 0; ni < 2; ni++) {
                mma16816(acc[ni], ah_reg[kk], &bh[ni * 2]);
                mma16816(acc[ni], al_reg[kk], &bh[ni * 2]);
                mma16816(acc[ni], ah_reg[kk], &bl[ni * 2]);
            }
        }
        // write S tile to smem (scaled)
        int col0 = t * 64 + wn * 16;
#pragma unroll
        for (int ni = 0; ni < 2; ni++)
#pragma unroll
            for (int half = 0; half < 2; half++) {
                int row = wm * 16 + gid + half * 8;
                int col = col0 + ni * 8 + tig * 2;
                *(float2*)(Ss + row * S_PITCH + col) =
                    make_float2(acc[ni][half * 2] * SCALE, acc[ni][half * 2 + 1] * SCALE);
            }
        __syncthreads();
        if (t + 2 < 16) {
            uint32_t nbuf = sb + SM_B + (t & 1) * B_BUF;
#pragma unroll
            for (int i = tid; i < 1024; i += 256) {
                int row = i >> 4, ch = i & 15;
                uint32_t d = nbuf + row * ROWQ + ch * 16;
                size_t o = (size_t)(t + 2) * 64 * 256 + (size_t)row * 256 + ch * 16;
                cp16(d, Kh + o);
                cp16(d + B_HL, Kl + o);
            }
        }
        CP_COMMIT();
    }
    __syncthreads();

    // ---- prefetch V tile 0 into spare region (overlaps softmax) ----
    {
        uint32_t vb = sb + SM_V0;
#pragma unroll
        for (int i = tid; i < 1024; i += 256) {
            int row = i >> 3, ch = i & 7;
            cp16(vb + row * VROWB + ch * 16, Vt + (size_t)row * 2048 + ch * 16);
        }
        CP_COMMIT();
    }

    // ---- softmax phase: warp w handles rows w*4 .. w*4+3 ----
    const int mode = g_maskmode;
#pragma unroll 1
    for (int j = 0; j < 4; j++) {
        int r = w * 4 + j;
        int q = q0 + r;
        const float* srow = Ss + r * S_PITCH;
        const size_t mrow = ((size_t)b * 1024 + q) * 1024;

        float v[32];
        float mx = -3.4e38f;
#pragma unroll
        for (int c8 = 0; c8 < 8; c8++) {
            int col = c8 * 128 + lane * 4;
            float4 x = *(const float4*)(srow + col);
            int m0i, m1i, m2i, m3i;
            if (mode == 0) {
                int4 mv = *(const int4*)((const int*)mask + mrow + col);
                m0i = mv.x; m1i = mv.y; m2i = mv.z; m3i = mv.w;
            } else if (mode == 1) {
                float4 mv = *(const float4*)((const float*)mask + mrow + col);
                m0i = (mv.x != 0.f); m1i = (mv.y != 0.f); m2i = (mv.z != 0.f); m3i = (mv.w != 0.f);
            } else {
                uchar4 mv = *(const uchar4*)((const unsigned char*)mask + mrow + col);
                m0i = mv.x; m1i = mv.y; m2i = mv.z; m3i = mv.w;
            }
            v[c8*4+0] = m0i ? NEGV : x.x;
            v[c8*4+1] = m1i ? NEGV : x.y;
            v[c8*4+2] = m2i ? NEGV : x.z;
            v[c8*4+3] = m3i ? NEGV : x.w;
            mx = fmaxf(mx, fmaxf(fmaxf(v[c8*4+0], v[c8*4+1]), fmaxf(v[c8*4+2], v[c8*4+3])));
        }
#pragma unroll
        for (int s = 16; s > 0; s >>= 1)
            mx = fmaxf(mx, __shfl_xor_sync(0xFFFFFFFFu, mx, s));

        float sum = 0.f;
#pragma unroll
        for (int i = 0; i < 32; i++) {
            v[i] = expf(v[i] - mx);
            sum += v[i];
        }
#pragma unroll
        for (int s = 16; s > 0; s >>= 1)
            sum += __shfl_xor_sync(0xFFFFFFFFu, sum, s);

        float inv = qmask[b * 1024 + q] / sum;
        float* prow = attn + ((size_t)hb * 1024 + q) * 1024;
        uint32_t phrow = sb + SM_PH + (uint32_t)r * PH_PITCH;
#pragma unroll
        for (int c8 = 0; c8 < 8; c8++) {
            int col = c8 * 128 + lane * 4;
            float p0 = v[c8*4+0] * inv, p1 = v[c8*4+1] * inv;
            float p2 = v[c8*4+2] * inv, p3 = v[c8*4+3] * inv;
            *(float4*)(prow + col) = make_float4(p0, p1, p2, p3);
            uint32_t hw0 = pack2h(p0, p1), hw1 = pack2h(p2, p3);
            asm volatile("st.shared.v2.b32 [%0], {%1,%2};"
                         :: "r"(phrow + (uint32_t)col * 2), "r"(hw0), "r"(hw1));
        }
    }
    __syncthreads();   // Ph complete; Ss free for V buffers

    // ---- PV phase: O[32x128] = Ph @ Vt, 16 key-chunks, double-buffered ----
    float oacc[2][2][4];
#pragma unroll
    for (int mi = 0; mi < 2; mi++)
#pragma unroll
        for (int ni = 0; ni < 2; ni++)
#pragma unroll
            for (int k = 0; k < 4; k++) oacc[mi][ni][k] = 0.f;

    for (int t = 0; t < 16; t++) {
        if (t + 1 < 16) {
            uint32_t vb = sb + (t & 1) * VBUF_BYTES;   // buffer for tile t+1 (in Ss region)
#pragma unroll
            for (int i = tid; i < 1024; i += 256) {
                int row = i >> 3, ch = i & 7;
                cp16(vb + row * VROWB + ch * 16,
                     Vt + (size_t)row * 2048 + (size_t)(t + 1) * 128 + ch * 16);
            }
        }
        CP_COMMIT();
        CP_WAIT(1);
        __syncthreads();
        uint32_t vb = (t == 0) ? (sb + SM_V0) : (sb + ((t - 1) & 1) * VBUF_BYTES);
#pragma unroll
        for (int kk = 0; kk < 4; kk++) {
            uint32_t a0[4], a1[4], bb[4];
            uint32_t abase = sb + SM_PH + (uint32_t)(lane & 15) * PH_PITCH
                             + t * 128 + kk * 32 + ((lane >> 4) & 1) * 16;
            ldm_x4(a0, abase);
            ldm_x4(a1, abase + 16 * PH_PITCH);
            uint32_t bbase = vb + (uint32_t)(w * 16 + ((lane >> 4) << 3) + (lane & 7)) * VROWB
                             + ((lane >> 3) & 1) * 16 + kk * 32;
            ldm_x4(bb, bbase);
            mma16816(oacc[0][0], a0, &bb[0]);
            mma16816(oacc[0][1], a0, &bb[2]);
            mma16816(oacc[1][0], a1, &bb[0]);
            mma16816(oacc[1][1], a1, &bb[2]);
        }
        __syncthreads();
    }

    // ---- O epilogue: warp w owns cols [16w, 16w+16) of head h ----
#pragma unroll
    for (int mi = 0; mi < 2; mi++)
#pragma unroll
        for (int ni = 0; ni < 2; ni++) {
            int col = h * 128 + w * 16 + ni * 8 + (lane & 3) * 2;
#pragma unroll
            for (int half = 0; half < 2; half++) {
                int q = q0 + mi * 16 + (lane >> 2) + half * 8;
                float d0 = oacc[mi][ni][half * 2], d1 = oacc[mi][ni][half * 2 + 1];
                *(uint32_t*)(g_Oh + ((size_t)b * 1024 + q) * 1024 + col) = pack2h(d0, d1);
            }
        }
}

// ---------------------------------------------------------------------------
// Final GEMM (HMMA): X = [dec | O] @ Wf + bf + dec  (K = 2048)
// dec-half 3-term; O-half 1-term.
// ---------------------------------------------------------------------------
__global__ __launch_bounds__(256, 1) void final_mma_kernel(
    const float* __restrict__ dec, const float* __restrict__ bf) {
    extern __shared__ char smem[];
    uint32_t sb = smem_to_u32(smem);
    int tid = threadIdx.x, lane = tid & 31, w = tid >> 5;
    int m0 = (w & 3) * 32, n0 = (w >> 2) * 64;
    int bx = blockIdx.x, by = blockIdx.y;
    const size_t arow0 = (size_t)by * 128;

    const __nv_bfloat16* Bh = g_Wft_h + (size_t)bx * 128 * 2048;
    const __nv_bfloat16* Bl = g_Wft_l + (size_t)bx * 128 * 2048;

    float acc[2][8][4];
    ACC_ZERO();

#define LOADC(cc, buf) do { \
    int _k0 = (cc) * 32; \
    if (_k0 < 1024) \
        load_chunk_t<3>((buf), g_dech + arow0*1024 + _k0, g_decl + arow0*1024 + _k0, \
                        Bh + _k0, Bl + _k0, 1024, 2048, tid); \
    else \
        load_chunk_t<1>((buf), g_Oh + arow0*1024 + (_k0 - 1024), nullptr, \
                        Bh + _k0, nullptr, 1024, 2048, tid); \
} while (0)
#define COMPUTEC(cc, buf) do { \
    if ((cc) < 32) compute_chunk_t<3>((buf), lane, m0, n0, acc); \
    else           compute_chunk_t<1>((buf), lane, m0, n0, acc); \
} while (0)
    PIPELINE3(64, BUF_BYTES, LOADC, COMPUTEC);
#undef LOADC
#undef COMPUTEC

#pragma unroll
    for (int mi = 0; mi < 2; mi++)
#pragma unroll
        for (int ni = 0; ni < 8; ni++) {
            int cc = bx * 128 + n0 + ni * 8 + (lane & 3) * 2;
            float2 bv = *(const float2*)(bf + cc);
#pragma unroll
            for (int half = 0; half < 2; half++) {
                int rr = by * 128 + m0 + mi * 16 + (lane >> 2) + half * 8;
                float d0 = acc[mi][ni][half * 2], d1 = acc[mi][ni][half * 2 + 1];
                float2 dv = *(const float2*)(dec + (size_t)rr * 1024 + cc);
                *(float2*)(g_X + (size_t)rr * 1024 + cc) =
                    make_float2(d0 + bv.x + dv.x, d1 + bv.y + dv.y);
            }
        }
}

// ---------------------------------------------------------------------------
// LayerNorm
// ---------------------------------------------------------------------------
__global__ __launch_bounds__(256) void ln_kernel(
    const float* __restrict__ gamma, const float* __restrict__ beta,
    float* __restrict__ out) {
    const int rowid = blockIdx.x;
    const int tid = threadIdx.x;
    const float* rp = g_X + (size_t)rowid * 1024;

    float4 x = *(const float4*)(rp + tid * 4);
    __shared__ float red[256];
    red[tid] = x.x + x.y + x.z + x.w;
    __syncthreads();
#pragma unroll
    for (int s = 128; s > 0; s >>= 1) {
        if (tid < s) red[tid] += red[tid + s];
        __syncthreads();
    }
    float mean = red[0] * (1.0f / 1024.0f);
    __syncthreads();

    float d0 = x.x - mean, d1 = x.y - mean, d2 = x.z - mean, d3 = x.w - mean;
    red[tid] = d0 * d0 + d1 * d1 + d2 * d2 + d3 * d3;
    __syncthreads();
#pragma unroll
    for (int s = 128; s > 0; s >>= 1) {
        if (tid < s) red[tid] += red[tid + s];
        __syncthreads();
    }
    float var = red[0] * (1.0f / 1024.0f);
    float inv = rsqrtf(var + 1e-5f);

    float4 g = *(const float4*)(gamma + tid * 4);
    float4 bt = *(const float4*)(beta + tid * 4);
    float* optr = out + (size_t)rowid * 1024 + tid * 4;
    *(float4*)optr = make_float4(d0 * inv * g.x + bt.x,
                                 d1 * inv * g.y + bt.y,
                                 d2 * inv * g.z + bt.z,
                                 d3 * inv * g.w + bt.w);
}

// ---------------------------------------------------------------------------
extern "C" void kernel_launch(void* const* d_in, const int* in_sizes, int n_in,
                              void* d_out, int out_size) {
    (void)in_sizes; (void)n_in; (void)out_size;
    const float* mem   = (const float*)d_in[0];
    const float* dec   = (const float*)d_in[1];
    const float* qmask = (const float*)d_in[2];
    const float* Wk    = (const float*)d_in[3];
    const float* Wv    = (const float*)d_in[4];
    const float* Wq    = (const float*)d_in[5];
    const float* Wf    = (const float*)d_in[6];
    const float* bf    = (const float*)d_in[7];
    const float* gamma = (const float*)d_in[8];
    const float* beta  = (const float*)d_in[9];
    const void*  mask  = d_in[10];

    float* out  = (float*)d_out;
    float* attn = out + XSIZE;

    cudaFuncSetAttribute(projKQ_mma_kernel, cudaFuncAttributeMaxDynamicSharedMemorySize, SMEM_TOT);
    cudaFuncSetAttribute(projV_mma_kernel,  cudaFuncAttributeMaxDynamicSharedMemorySize, SMEM1_TOT);
    cudaFuncSetAttribute(attn_fused_kernel, cudaFuncAttributeMaxDynamicSharedMemorySize, SMEM_ATTN);
    cudaFuncSetAttribute(final_mma_kernel,  cudaFuncAttributeMaxDynamicSharedMemorySize, SMEM_TOT);

    detect_mask_kernel<<<1, 32>>>(mask);
    conv_hilo_kernel<<<8192, 256>>>(mem, 0, XSIZE / 4);
    conv_hilo_kernel<<<8192, 256>>>(dec, 1, XSIZE / 4);
    convT_kernel<<<dim3(32, 32), dim3(32, 8)>>>(Wk, 0, 1024, 1024);
    convT_kernel<<<dim3(32, 32), dim3(32, 8)>>>(Wv, 1, 1024, 1024);
    convT_kernel<<<dim3(32, 32), dim3(32, 8)>>>(Wq, 2, 1024, 1024);
    convT_kernel<<<dim3(32, 64), dim3(32, 8)>>>(Wf, 3, 2048, 1024);

    projKQ_mma_kernel<<<dim3(8, 64, 2), 256, SMEM_TOT>>>();
    projV_mma_kernel<<<dim3(8, 64), 256, SMEM1_TOT>>>();
    transposeV_kernel<<<dim3(4, 32, 64), dim3(32, 8)>>>();
    attn_fused_kernel<<<dim3(32, 64), 256, SMEM_ATTN>>>(attn, qmask, mask);
    final_mma_kernel<<<dim3(8, 64), 256, SMEM_TOT>>>(dec, bf);
    ln_kernel<<<8192, 256>>>(gamma, beta, out);
}

// round 10
// speedup vs baseline: 1.1201x; 1.1201x over previous
#include <cuda_runtime.h>
#include <cuda_bf16.h>
#include <cstdint>
#include <math.h>

// ---------------------------------------------------------------------------
// Problem constants
// ---------------------------------------------------------------------------
#define NB 8
#define SQ 1024
#define SK 1024
#define DD 1024
#define NH 8
#define DH 128
#define HB (NH*NB)              // 64
#define XSIZE (NB*SQ*DD)        // 8388608
#define NEGV (-4294967295.0f)
#define SCALE 0.0883883476483184405f

// K32-chunk buffers (1-term kernels): 128 rows x 32 bf16, pitch 80B
#define ROWB 80
#define OP_BYTES (128*ROWB)       // 10240
#define BUF1_BYTES (2*OP_BYTES)   // 20480  (Ah,Bh)
#define SMEM1_TOT (3*BUF1_BYTES)  // 61440

// K64-chunk buffers (3-term kernels): 128 rows x 64 bf16, pitch 144B
#define ROWB2 144
#define OP2_BYTES (128*ROWB2)     // 18432
#define OFF2_AL (1*OP2_BYTES)
#define OFF2_BH (2*OP2_BYTES)
#define OFF2_BL (3*OP2_BYTES)
#define BUF2_BYTES (4*OP2_BYTES)  // 73728
#define SMEM2_TOT (2*BUF2_BYTES)  // 147456

// attn_fused smem layout (R8 proven)
#define ROWQ 272                  // 256B data + 16B skew
#define S_PITCH 1032              // fp32 words per S row (skewed)
#define SM_Q (32*S_PITCH*4)       // 132096
#define B_HL (64*ROWQ)            // 17408
#define B_BUF (2*B_HL)            // 34816
#define SM_B (SM_Q + 2*32*ROWQ)   // 149504
#define SMEM_ATTN (SM_B + 2*B_BUF) // 219136

// ---------------------------------------------------------------------------
// Scratch (device globals — referenced ONLY from device code)
// ---------------------------------------------------------------------------
__device__ __nv_bfloat16 g_memh[NB*SK*DD], g_meml[NB*SK*DD];
__device__ __nv_bfloat16 g_dech[NB*SQ*DD], g_decl[NB*SQ*DD];
__device__ __nv_bfloat16 g_Wkt_h[DD*DD], g_Wkt_l[DD*DD];
__device__ __nv_bfloat16 g_Wvt_h[DD*DD];
__device__ __nv_bfloat16 g_Wqt_h[DD*DD], g_Wqt_l[DD*DD];
__device__ __nv_bfloat16 g_Wft_h[DD*2*DD], g_Wft_l[DD*2*DD];
__device__ __nv_bfloat16 g_Kh[HB*SK*DH], g_Kl[HB*SK*DH];
__device__ __nv_bfloat16 g_Qh[HB*SQ*DH], g_Ql[HB*SQ*DH];
__device__ __nv_bfloat16 g_Vh[HB*SK*DH];          // [hb][s][d] bf16
__device__ __nv_bfloat16 g_Vth[HB*DH*SK];         // [hb][d][s] bf16
__device__ __nv_bfloat16 g_Ph[(size_t)HB*SQ*SK];
__device__ __nv_bfloat16 g_Oh[NB*SQ*DD];
__device__ float         g_X[NB*SQ*DD];
__device__ int           g_maskmode;

// ---------------------------------------------------------------------------
// Helpers
// ---------------------------------------------------------------------------
__device__ __forceinline__ uint32_t smem_to_u32(const void* p) {
    uint32_t a;
    asm("{ .reg .u64 t; cvta.to.shared.u64 t, %1; cvt.u32.u64 %0, t; }" : "=r"(a) : "l"(p));
    return a;
}

__device__ __forceinline__ void cp16(uint32_t dst, const void* src) {
    asm volatile("cp.async.cg.shared.global [%0], [%1], 16;" :: "r"(dst), "l"(src));
}
#define CP_COMMIT() asm volatile("cp.async.commit_group;" ::: "memory")
#define CP_WAIT(n)  asm volatile("cp.async.wait_group %0;" :: "n"(n) : "memory")

__device__ __forceinline__ void ldm_x4(uint32_t* r, uint32_t addr) {
    asm volatile("ldmatrix.sync.aligned.m8n8.x4.shared.b16 {%0,%1,%2,%3}, [%4];"
        : "=r"(r[0]), "=r"(r[1]), "=r"(r[2]), "=r"(r[3]) : "r"(addr));
}

__device__ __forceinline__ void mma16816(float* d, const uint32_t* a, const uint32_t* b) {
    asm volatile("mma.sync.aligned.m16n8k16.row.col.f32.bf16.bf16.f32 "
        "{%0,%1,%2,%3}, {%4,%5,%6,%7}, {%8,%9}, {%0,%1,%2,%3};"
        : "+f"(d[0]), "+f"(d[1]), "+f"(d[2]), "+f"(d[3])
        : "r"(a[0]), "r"(a[1]), "r"(a[2]), "r"(a[3]), "r"(b[0]), "r"(b[1]));
}

__device__ __forceinline__ void split_hilo(float v, __nv_bfloat16& h, __nv_bfloat16& l) {
    h = __float2bfloat16(v);
    l = __float2bfloat16(v - __bfloat162float(h));
}
__device__ __forceinline__ uint32_t pack2h(float v0, float v1) {
    __nv_bfloat16 h0, l0, h1, l1;
    split_hilo(v0, h0, l0); split_hilo(v1, h1, l1);
    __nv_bfloat162 p = __halves2bfloat162(h0, h1);
    return *reinterpret_cast<uint32_t*>(&p);
}
__device__ __forceinline__ uint32_t pack2l(float v0, float v1) {
    __nv_bfloat16 h0, l0, h1, l1;
    split_hilo(v0, h0, l0); split_hilo(v1, h1, l1);
    __nv_bfloat162 p = __halves2bfloat162(l0, l1);
    return *reinterpret_cast<uint32_t*>(&p);
}

#define ACC_ZERO() do { \
    _Pragma("unroll") for (int _i = 0; _i < 2; _i++) \
    _Pragma("unroll") for (int _j = 0; _j < 8; _j++) \
    _Pragma("unroll") for (int _k = 0; _k < 4; _k++) acc[_i][_j][_k] = 0.f; \
} while (0)

// ---------------------------------------------------------------------------
// K32-chunk, 1-term building blocks (projV, pv) — R8 proven
// ---------------------------------------------------------------------------
__device__ __forceinline__ void load_chunk1(
    uint32_t sbuf, const __nv_bfloat16* __restrict__ Ah,
    const __nv_bfloat16* __restrict__ Bh, int lda, int ldb, int tid)
{
#pragma unroll
    for (int i = tid; i < 512; i += 256) {
        int row = i >> 2, ch = i & 3;
        uint32_t d = sbuf + row*ROWB + ch*16;
        cp16(d,            (const char*)Ah + (size_t)row * lda * 2 + ch*16);
        cp16(d + OP_BYTES, (const char*)Bh + (size_t)row * ldb * 2 + ch*16);
    }
}

__device__ __forceinline__ void compute_chunk1(uint32_t sbuf, int lane, int m0, int n0,
                                               float acc[2][8][4])
{
#pragma unroll
    for (int kk = 0; kk < 2; kk++) {
        uint32_t ah[2][4];
        int arow = m0 + (lane & 15);
        uint32_t abase = sbuf + kk*32 + ((lane >> 4) & 1)*16;
        ldm_x4(ah[0], abase + arow*ROWB);
        ldm_x4(ah[1], abase + (arow + 16)*ROWB);

        uint32_t bh[4][4];
        int brow = n0 + ((lane >> 4) << 3) + (lane & 7);
        uint32_t bko = ((lane >> 3) & 1) * 16 + kk*32;
#pragma unroll
        for (int nb = 0; nb < 4; nb++)
            ldm_x4(bh[nb], sbuf + OP_BYTES + (brow + nb*16)*ROWB + bko);
#pragma unroll
        for (int mi = 0; mi < 2; mi++)
#pragma unroll
            for (int ni = 0; ni < 8; ni++)
                mma16816(acc[mi][ni], ah[mi], &bh[ni >> 1][(ni & 1) * 2]);
    }
}

// 3-stage pipeline driver (K32 kernels)
#define PIPELINE3(KC, BUFSZ, LOADC, COMPUTEC) do { \
    { LOADC(0, sb + 0*(BUFSZ)); } CP_COMMIT(); \
    { LOADC(1, sb + 1*(BUFSZ)); } CP_COMMIT(); \
    for (int c = 0; c < (KC); c++) { \
        if (c + 2 < (KC)) { LOADC((c + 2), sb + ((c + 2) % 3)*(BUFSZ)); } \
        CP_COMMIT(); \
        CP_WAIT(2); \
        __syncthreads(); \
        { COMPUTEC(c, sb + (c % 3)*(BUFSZ)); } \
        __syncthreads(); \
    } \
} while (0)

// ---------------------------------------------------------------------------
// K64-chunk building blocks (projKQ, final). TERMS=3 or 1; Bh always at OFF2_BH.
// ---------------------------------------------------------------------------
template<int TERMS>
__device__ __forceinline__ void load_chunk64(
    uint32_t sbuf,
    const __nv_bfloat16* __restrict__ Ah, const __nv_bfloat16* __restrict__ Al,
    const __nv_bfloat16* __restrict__ Bh, const __nv_bfloat16* __restrict__ Bl,
    int lda, int ldb, int tid)
{
#pragma unroll
    for (int i = tid; i < 1024; i += 256) {
        int row = i >> 3, ch = i & 7;
        uint32_t d = sbuf + row*ROWB2 + ch*16;
        size_t ao = (size_t)row * lda * 2 + ch*16;
        size_t bo = (size_t)row * ldb * 2 + ch*16;
        cp16(d,           (const char*)Ah + ao);
        cp16(d + OFF2_BH, (const char*)Bh + bo);
        if (TERMS == 3) {
            cp16(d + OFF2_AL, (const char*)Al + ao);
            cp16(d + OFF2_BL, (const char*)Bl + bo);
        }
    }
}

template<int TERMS>
__device__ __forceinline__ void compute_chunk64(uint32_t sbuf, int lane, int m0, int n0,
                                                float acc[2][8][4])
{
#pragma unroll
    for (int kk = 0; kk < 4; kk++) {
        uint32_t ah[2][4], al[2][4];
        int arow = m0 + (lane & 15);
        uint32_t abase = sbuf + kk*32 + ((lane >> 4) & 1)*16;
        ldm_x4(ah[0], abase + arow*ROWB2);
        ldm_x4(ah[1], abase + (arow + 16)*ROWB2);
        if (TERMS == 3) {
            ldm_x4(al[0], abase + OFF2_AL + arow*ROWB2);
            ldm_x4(al[1], abase + OFF2_AL + (arow + 16)*ROWB2);
        }

        uint32_t bh[4][4], bl[4][4];
        int brow = n0 + ((lane >> 4) << 3) + (lane & 7);
        uint32_t bko = ((lane >> 3) & 1) * 16 + kk*32;
#pragma unroll
        for (int nb = 0; nb < 4; nb++) {
            ldm_x4(bh[nb], sbuf + OFF2_BH + (brow + nb*16)*ROWB2 + bko);
            if (TERMS == 3)
                ldm_x4(bl[nb], sbuf + OFF2_BL + (brow + nb*16)*ROWB2 + bko);
        }
#pragma unroll
        for (int mi = 0; mi < 2; mi++)
#pragma unroll
            for (int ni = 0; ni < 8; ni++) {
                const uint32_t* BH = &bh[ni >> 1][(ni & 1) * 2];
                mma16816(acc[mi][ni], ah[mi], BH);
                if (TERMS == 3) {
                    const uint32_t* BL = &bl[ni >> 1][(ni & 1) * 2];
                    mma16816(acc[mi][ni], al[mi], BH);
                    mma16816(acc[mi][ni], ah[mi], BL);
                }
            }
    }
}

// 2-stage pipeline driver (K64 kernels)
#define PIPELINE2(KC, BUFSZ, LOADC, COMPUTEC) do { \
    { LOADC(0, sb); } CP_COMMIT(); \
    for (int c = 0; c < (KC); c++) { \
        if (c + 1 < (KC)) { \
            { LOADC((c + 1), sb + ((c + 1) & 1)*(BUFSZ)); } \
            CP_COMMIT(); \
            CP_WAIT(1); \
        } else CP_WAIT(0); \
        __syncthreads(); \
        { COMPUTEC(c, sb + (c & 1)*(BUFSZ)); } \
        __syncthreads(); \
    } \
} while (0)

// ---------------------------------------------------------------------------
// Mask dtype detection
// ---------------------------------------------------------------------------
__global__ void detect_mask_kernel(const void* __restrict__ mask) {
    int t = threadIdx.x;
    const int* pi = (const int*)mask;
    const float* pf = (const float*)mask;
    bool oki = true, okf = true;
    for (int i = t; i < 256; i += 32) {
        int v = pi[i];
        oki = oki && (v == 0 || v == 1);
        float f = pf[i];
        okf = okf && (f == 0.0f || f == 1.0f);
    }
    oki = __all_sync(0xFFFFFFFFu, oki);
    okf = __all_sync(0xFFFFFFFFu, okf);
    if (t == 0) g_maskmode = oki ? 0 : (okf ? 1 : 2);
}

// ---------------------------------------------------------------------------
// fp32 -> bf16 hi/lo. which=0 -> g_mem*, which=1 -> g_dec*
// ---------------------------------------------------------------------------
__global__ void conv_hilo_kernel(const float* __restrict__ src, int which, int n4) {
    __nv_bfloat16* __restrict__ dh = which ? g_dech : g_memh;
    __nv_bfloat16* __restrict__ dl = which ? g_decl : g_meml;
    int idx = blockIdx.x * blockDim.x + threadIdx.x;
    if (idx >= n4) return;
    float4 v = ((const float4*)src)[idx];
    uint2 hw, lw;
    hw.x = pack2h(v.x, v.y); hw.y = pack2h(v.z, v.w);
    lw.x = pack2l(v.x, v.y); lw.y = pack2l(v.z, v.w);
    ((uint2*)dh)[idx] = hw;
    ((uint2*)dl)[idx] = lw;
}

// ---------------------------------------------------------------------------
// W [K][N] fp32 -> Wt [N][K] bf16 hi/lo. which: 0=Wk 1=Wv(hi only) 2=Wq 3=Wf
// ---------------------------------------------------------------------------
__global__ void convT_kernel(const float* __restrict__ src, int which, int K, int N) {
    __nv_bfloat16 *dh, *dl;
    if (which == 0)      { dh = g_Wkt_h; dl = g_Wkt_l; }
    else if (which == 1) { dh = g_Wvt_h; dl = nullptr; }
    else if (which == 2) { dh = g_Wqt_h; dl = g_Wqt_l; }
    else                 { dh = g_Wft_h; dl = g_Wft_l; }

    __shared__ float t[32][33];
    int n0 = blockIdx.x * 32, k0 = blockIdx.y * 32;
    int tx = threadIdx.x;
    for (int i = threadIdx.y; i < 32; i += 8)
        t[i][tx] = src[(size_t)(k0 + i) * N + n0 + tx];
    __syncthreads();
    for (int i = threadIdx.y; i < 32; i += 8) {
        float v = t[tx][i];
        __nv_bfloat16 h, l;
        split_hilo(v, h, l);
        size_t o = (size_t)(n0 + i) * K + k0 + tx;
        dh[o] = h;
        if (dl) dl[o] = l;
    }
}

// ---------------------------------------------------------------------------
// V [hb][1024][128] bf16 -> Vt [hb][128][1024] bf16 (16-bit move)
// ---------------------------------------------------------------------------
__global__ void transposeV_kernel() {
    __shared__ unsigned short t[32][33];
    int hb = blockIdx.z;
    int d0 = blockIdx.x * 32, s0 = blockIdx.y * 32;
    int tx = threadIdx.x;
    const unsigned short* src = (const unsigned short*)g_Vh + (size_t)hb * SK * DH;
    for (int i = threadIdx.y; i < 32; i += 8)
        t[i][tx] = src[(size_t)(s0 + i) * 128 + d0 + tx];
    __syncthreads();
    for (int i = threadIdx.y; i < 32; i += 8) {
        size_t o = (size_t)hb * DH * SK + (size_t)(d0 + i) * 1024 + s0 + tx;
        ((unsigned short*)g_Vth)[o] = t[tx][i];
    }
}

// ---------------------------------------------------------------------------
// Projection GEMM K/Q (HMMA, 3-term, K64 chunks): z=0 K, z=1 Q.
// ---------------------------------------------------------------------------
__global__ __launch_bounds__(256, 1) void projKQ_mma_kernel() {
    extern __shared__ char smem[];
    uint32_t sb = smem_to_u32(smem);
    int tid = threadIdx.x, lane = tid & 31, w = tid >> 5;
    int m0 = (w & 3) * 32, n0 = (w >> 2) * 64;
    int bx = blockIdx.x, by = blockIdx.y, z = blockIdx.z;

    const __nv_bfloat16* Ah = ((z == 1) ? g_dech : g_memh) + (size_t)by * 128 * 1024;
    const __nv_bfloat16* Al = ((z == 1) ? g_decl : g_meml) + (size_t)by * 128 * 1024;
    const __nv_bfloat16* Bh = ((z == 0) ? g_Wkt_h : g_Wqt_h) + (size_t)bx * 128 * 1024;
    const __nv_bfloat16* Bl = ((z == 0) ? g_Wkt_l : g_Wqt_l) + (size_t)bx * 128 * 1024;

    float acc[2][8][4];
    ACC_ZERO();

#define LOADC(cc, buf) load_chunk64<3>((buf), Ah + (cc)*64, Al + (cc)*64, Bh + (cc)*64, Bl + (cc)*64, 1024, 1024, tid)
#define COMPUTEC(cc, buf) compute_chunk64<3>((buf), lane, m0, n0, acc)
    PIPELINE2(16, BUF2_BYTES, LOADC, COMPUTEC);
#undef LOADC
#undef COMPUTEC

#pragma unroll
    for (int mi = 0; mi < 2; mi++)
#pragma unroll
        for (int ni = 0; ni < 8; ni++) {
            int cc = n0 + ni * 8 + (lane & 3) * 2;
#pragma unroll
            for (int half = 0; half < 2; half++) {
                int rr = by * 128 + m0 + mi * 16 + (lane >> 2) + half * 8;
                float d0 = acc[mi][ni][half * 2], d1 = acc[mi][ni][half * 2 + 1];
                int bb = rr >> 10, ss = rr & 1023;
                size_t base = (((size_t)(bx * 8 + bb)) * 1024 + ss) * 128 + cc;
                __nv_bfloat16* oh = (z == 0) ? g_Kh : g_Qh;
                __nv_bfloat16* ol = (z == 0) ? g_Kl : g_Ql;
                *(uint32_t*)(oh + base) = pack2h(d0, d1);
                *(uint32_t*)(ol + base) = pack2l(d0, d1);
            }
        }
}

// ---------------------------------------------------------------------------
// Projection GEMM V (HMMA, 1-term, K32, compact smem): bf16 head-split out
// ---------------------------------------------------------------------------
__global__ __launch_bounds__(256, 2) void projV_mma_kernel() {
    extern __shared__ char smem[];
    uint32_t sb = smem_to_u32(smem);
    int tid = threadIdx.x, lane = tid & 31, w = tid >> 5;
    int m0 = (w & 3) * 32, n0 = (w >> 2) * 64;
    int bx = blockIdx.x, by = blockIdx.y;

    const __nv_bfloat16* Ah = g_memh + (size_t)by * 128 * 1024;
    const __nv_bfloat16* Bh = g_Wvt_h + (size_t)bx * 128 * 1024;

    float acc[2][8][4];
    ACC_ZERO();

#define LOADC(cc, buf) load_chunk1((buf), Ah + (cc)*32, Bh + (cc)*32, 1024, 1024, tid)
#define COMPUTEC(cc, buf) compute_chunk1((buf), lane, m0, n0, acc)
    PIPELINE3(32, BUF1_BYTES, LOADC, COMPUTEC);
#undef LOADC
#undef COMPUTEC

#pragma unroll
    for (int mi = 0; mi < 2; mi++)
#pragma unroll
        for (int ni = 0; ni < 8; ni++) {
            int cc = n0 + ni * 8 + (lane & 3) * 2;
#pragma unroll
            for (int half = 0; half < 2; half++) {
                int rr = by * 128 + m0 + mi * 16 + (lane >> 2) + half * 8;
                float d0 = acc[mi][ni][half * 2], d1 = acc[mi][ni][half * 2 + 1];
                int bb = rr >> 10, ss = rr & 1023;
                size_t base = (((size_t)(bx * 8 + bb)) * 1024 + ss) * 128 + cc;
                *(uint32_t*)(g_Vh + base) = pack2h(d0, d1);
            }
        }
}

// ---------------------------------------------------------------------------
// FUSED scores+softmax (R8 proven): one CTA = 32 query rows x 1024 keys.
// S in smem; writes P fp32 (attns output) + Ph bf16 to global.
// ---------------------------------------------------------------------------
__global__ __launch_bounds__(256, 1) void attn_fused_kernel(
    float* __restrict__ attn, const float* __restrict__ qmask,
    const void* __restrict__ mask)
{
    extern __shared__ char smem[];
    uint32_t sb = smem_to_u32(smem);
    float* Ss = (float*)smem;
    int tid = threadIdx.x, lane = tid & 31, w = tid >> 5;
    const int wm = w >> 2;
    const int wn = w & 3;
    int blk = blockIdx.x;
    int y = blockIdx.y;
    int h = y & 7, b = y >> 3;
    int hb = h * 8 + b;
    int q0 = blk * 32;

    const char* Qh = (const char*)(g_Qh + ((size_t)hb * 1024 + q0) * 128);
    const char* Ql = (const char*)(g_Ql + ((size_t)hb * 1024 + q0) * 128);
    const char* Kh = (const char*)(g_Kh + (size_t)hb * 1024 * 128);
    const char* Kl = (const char*)(g_Kl + (size_t)hb * 1024 * 128);

#pragma unroll
    for (int i = tid; i < 512; i += 256) {
        int row = i >> 4, ch = i & 15;
        uint32_t d = sb + SM_Q + row * ROWQ + ch * 16;
        size_t o = (size_t)row * 256 + ch * 16;
        cp16(d, Qh + o);
        cp16(d + 32 * ROWQ, Ql + o);
    }
    CP_COMMIT();

#pragma unroll
    for (int t = 0; t < 2; t++) {
        uint32_t bbuf = sb + SM_B + t * B_BUF;
#pragma unroll
        for (int i = tid; i < 1024; i += 256) {
            int row = i >> 4, ch = i & 15;
            uint32_t d = bbuf + row * ROWQ + ch * 16;
            size_t o = (size_t)t * 64 * 256 + (size_t)row * 256 + ch * 16;
            cp16(d, Kh + o);
            cp16(d + B_HL, Kl + o);
        }
        CP_COMMIT();
    }

    CP_WAIT(2);
    __syncthreads();
    uint32_t ah_reg[8][4], al_reg[8][4];
    {
        uint32_t abase = sb + SM_Q + (uint32_t)(wm * 16 + (lane & 15)) * ROWQ
                         + ((lane >> 4) & 1) * 16;
#pragma unroll
        for (int kk = 0; kk < 8; kk++) {
            ldm_x4(ah_reg[kk], abase + kk * 32);
            ldm_x4(al_reg[kk], abase + 32 * ROWQ + kk * 32);
        }
    }

    const int gid = lane >> 2, tig = lane & 3;
    for (int t = 0; t < 16; t++) {
        CP_WAIT(1);
        __syncthreads();
        uint32_t bbuf = sb + SM_B + (t & 1) * B_BUF;
        float acc[2][4];
#pragma unroll
        for (int ni = 0; ni < 2; ni++)
#pragma unroll
            for (int k = 0; k < 4; k++) acc[ni][k] = 0.f;

        uint32_t bbase = bbuf + (uint32_t)(wn * 16 + ((lane >> 4) << 3) + (lane & 7)) * ROWQ
                         + ((lane >> 3) & 1) * 16;
#pragma unroll
        for (int kk = 0; kk < 8; kk++) {
            uint32_t bh[4], bl[4];
            ldm_x4(bh, bbase + kk * 32);
            ldm_x4(bl, bbase + B_HL + kk * 32);
#pragma unroll
            for (int ni = 0; ni < 2; ni++) {
                mma16816(acc[ni], ah_reg[kk], &bh[ni * 2]);
                mma16816(acc[ni], al_reg[kk], &bh[ni * 2]);
                mma16816(acc[ni], ah_reg[kk], &bl[ni * 2]);
            }
        }
        int col0 = t * 64 + wn * 16;
#pragma unroll
        for (int ni = 0; ni < 2; ni++)
#pragma unroll
            for (int half = 0; half < 2; half++) {
                int row = wm * 16 + gid + half * 8;
                int col = col0 + ni * 8 + tig * 2;
                *(float2*)(Ss + row * S_PITCH + col) =
                    make_float2(acc[ni][half * 2] * SCALE, acc[ni][half * 2 + 1] * SCALE);
            }
        __syncthreads();
        if (t + 2 < 16) {
            uint32_t nbuf = sb + SM_B + (t & 1) * B_BUF;
#pragma unroll
            for (int i = tid; i < 1024; i += 256) {
                int row = i >> 4, ch = i & 15;
                uint32_t d = nbuf + row * ROWQ + ch * 16;
                size_t o = (size_t)(t + 2) * 64 * 256 + (size_t)row * 256 + ch * 16;
                cp16(d, Kh + o);
                cp16(d + B_HL, Kl + o);
            }
        }
        CP_COMMIT();
    }
    __syncthreads();

    const int mode = g_maskmode;
#pragma unroll 1
    for (int j = 0; j < 4; j++) {
        int r = w * 4 + j;
        int q = q0 + r;
        const float* srow = Ss + r * S_PITCH;
        const size_t mrow = ((size_t)b * 1024 + q) * 1024;

        float v[32];
        float mx = -3.4e38f;
#pragma unroll
        for (int c8 = 0; c8 < 8; c8++) {
            int col = c8 * 128 + lane * 4;
            float4 x = *(const float4*)(srow + col);
            int m0i, m1i, m2i, m3i;
            if (mode == 0) {
                int4 mv = *(const int4*)((const int*)mask + mrow + col);
                m0i = mv.x; m1i = mv.y; m2i = mv.z; m3i = mv.w;
            } else if (mode == 1) {
                float4 mv = *(const float4*)((const float*)mask + mrow + col);
                m0i = (mv.x != 0.f); m1i = (mv.y != 0.f); m2i = (mv.z != 0.f); m3i = (mv.w != 0.f);
            } else {
                uchar4 mv = *(const uchar4*)((const unsigned char*)mask + mrow + col);
                m0i = mv.x; m1i = mv.y; m2i = mv.z; m3i = mv.w;
            }
            v[c8*4+0] = m0i ? NEGV : x.x;
            v[c8*4+1] = m1i ? NEGV : x.y;
            v[c8*4+2] = m2i ? NEGV : x.z;
            v[c8*4+3] = m3i ? NEGV : x.w;
            mx = fmaxf(mx, fmaxf(fmaxf(v[c8*4+0], v[c8*4+1]), fmaxf(v[c8*4+2], v[c8*4+3])));
        }
#pragma unroll
        for (int s = 16; s > 0; s >>= 1)
            mx = fmaxf(mx, __shfl_xor_sync(0xFFFFFFFFu, mx, s));

        float sum = 0.f;
#pragma unroll
        for (int i = 0; i < 32; i++) {
            v[i] = expf(v[i] - mx);
            sum += v[i];
        }
#pragma unroll
        for (int s = 16; s > 0; s >>= 1)
            sum += __shfl_xor_sync(0xFFFFFFFFu, sum, s);

        float inv = qmask[b * 1024 + q] / sum;
        float* prow = attn + ((size_t)hb * 1024 + q) * 1024;
        __nv_bfloat16* phrow = g_Ph + ((size_t)hb * 1024 + q) * 1024;
#pragma unroll
        for (int c8 = 0; c8 < 8; c8++) {
            int col = c8 * 128 + lane * 4;
            float p0 = v[c8*4+0] * inv, p1 = v[c8*4+1] * inv;
            float p2 = v[c8*4+2] * inv, p3 = v[c8*4+3] * inv;
            *(float4*)(prow + col) = make_float4(p0, p1, p2, p3);
            uint2 hw;
            hw.x = pack2h(p0, p1); hw.y = pack2h(p2, p3);
            *(uint2*)(phrow + col) = hw;
        }
    }
}

// ---------------------------------------------------------------------------
// PV GEMM (HMMA, 1-term, K32, compact smem): O = Ph @ Vt ; bf16 out
// ---------------------------------------------------------------------------
__global__ __launch_bounds__(256, 2) void pv_mma_kernel() {
    extern __shared__ char smem[];
    uint32_t sb = smem_to_u32(smem);
    int tid = threadIdx.x, lane = tid & 31, w = tid >> 5;
    int m0 = (w & 3) * 32, n0 = (w >> 2) * 64;
    int bx = blockIdx.x, hb = blockIdx.y;

    const __nv_bfloat16* Ah = g_Ph + ((size_t)hb * 1024 + bx * 128) * 1024;
    const __nv_bfloat16* Bh = g_Vth + (size_t)hb * DH * SK;

    float acc[2][8][4];
    ACC_ZERO();

#define LOADC(cc, buf) load_chunk1((buf), Ah + (cc)*32, Bh + (cc)*32, 1024, 1024, tid)
#define COMPUTEC(cc, buf) compute_chunk1((buf), lane, m0, n0, acc)
    PIPELINE3(32, BUF1_BYTES, LOADC, COMPUTEC);
#undef LOADC
#undef COMPUTEC

    const int b = hb & 7, h = hb >> 3;
#pragma unroll
    for (int mi = 0; mi < 2; mi++)
#pragma unroll
        for (int ni = 0; ni < 8; ni++) {
            int cc = n0 + ni * 8 + (lane & 3) * 2;
#pragma unroll
            for (int half = 0; half < 2; half++) {
                int q = bx * 128 + m0 + mi * 16 + (lane >> 2) + half * 8;
                float d0 = acc[mi][ni][half * 2], d1 = acc[mi][ni][half * 2 + 1];
                size_t base = ((size_t)b * 1024 + q) * 1024 + h * 128 + cc;
                *(uint32_t*)(g_Oh + base) = pack2h(d0, d1);
            }
        }
}

// ---------------------------------------------------------------------------
// Final GEMM (HMMA, K64 chunks): X = [dec | O] @ Wf + bf + dec  (K = 2048)
// chunks 0..15: dec-half 3-term; chunks 16..31: O-half 1-term.
// ---------------------------------------------------------------------------
__global__ __launch_bounds__(256, 1) void final_mma_kernel(
    const float* __restrict__ dec, const float* __restrict__ bf) {
    extern __shared__ char smem[];
    uint32_t sb = smem_to_u32(smem);
    int tid = threadIdx.x, lane = tid & 31, w = tid >> 5;
    int m0 = (w & 3) * 32, n0 = (w >> 2) * 64;
    int bx = blockIdx.x, by = blockIdx.y;
    const size_t arow0 = (size_t)by * 128;

    const __nv_bfloat16* Bh = g_Wft_h + (size_t)bx * 128 * 2048;
    const __nv_bfloat16* Bl = g_Wft_l + (size_t)bx * 128 * 2048;

    float acc[2][8][4];
    ACC_ZERO();

#define LOADC(cc, buf) do { \
    int _k0 = (cc) * 64; \
    if (_k0 < 1024) \
        load_chunk64<3>((buf), g_dech + arow0*1024 + _k0, g_decl + arow0*1024 + _k0, \
                        Bh + _k0, Bl + _k0, 1024, 2048, tid); \
    else \
        load_chunk64<1>((buf), g_Oh + arow0*1024 + (_k0 - 1024), nullptr, \
                        Bh + _k0, nullptr, 1024, 2048, tid); \
} while (0)
#define COMPUTEC(cc, buf) do { \
    if ((cc) < 16) compute_chunk64<3>((buf), lane, m0, n0, acc); \
    else           compute_chunk64<1>((buf), lane, m0, n0, acc); \
} while (0)
    PIPELINE2(32, BUF2_BYTES, LOADC, COMPUTEC);
#undef LOADC
#undef COMPUTEC

#pragma unroll
    for (int mi = 0; mi < 2; mi++)
#pragma unroll
        for (int ni = 0; ni < 8; ni++) {
            int cc = bx * 128 + n0 + ni * 8 + (lane & 3) * 2;
            float2 bv = *(const float2*)(bf + cc);
#pragma unroll
            for (int half = 0; half < 2; half++) {
                int rr = by * 128 + m0 + mi * 16 + (lane >> 2) + half * 8;
                float d0 = acc[mi][ni][half * 2], d1 = acc[mi][ni][half * 2 + 1];
                float2 dv = *(const float2*)(dec + (size_t)rr * 1024 + cc);
                *(float2*)(g_X + (size_t)rr * 1024 + cc) =
                    make_float2(d0 + bv.x + dv.x, d1 + bv.y + dv.y);
            }
        }
}

// ---------------------------------------------------------------------------
// LayerNorm
// ---------------------------------------------------------------------------
__global__ __launch_bounds__(256) void ln_kernel(
    const float* __restrict__ gamma, const float* __restrict__ beta,
    float* __restrict__ out) {
    const int rowid = blockIdx.x;
    const int tid = threadIdx.x;
    const float* rp = g_X + (size_t)rowid * 1024;

    float4 x = *(const float4*)(rp + tid * 4);
    __shared__ float red[256];
    red[tid] = x.x + x.y + x.z + x.w;
    __syncthreads();
#pragma unroll
    for (int s = 128; s > 0; s >>= 1) {
        if (tid < s) red[tid] += red[tid + s];
        __syncthreads();
    }
    float mean = red[0] * (1.0f / 1024.0f);
    __syncthreads();

    float d0 = x.x - mean, d1 = x.y - mean, d2 = x.z - mean, d3 = x.w - mean;
    red[tid] = d0 * d0 + d1 * d1 + d2 * d2 + d3 * d3;
    __syncthreads();
#pragma unroll
    for (int s = 128; s > 0; s >>= 1) {
        if (tid < s) red[tid] += red[tid + s];
        __syncthreads();
    }
    float var = red[0] * (1.0f / 1024.0f);
    float inv = rsqrtf(var + 1e-5f);

    float4 g = *(const float4*)(gamma + tid * 4);
    float4 bt = *(const float4*)(beta + tid * 4);
    float* optr = out + (size_t)rowid * 1024 + tid * 4;
    *(float4*)optr = make_float4(d0 * inv * g.x + bt.x,
                                 d1 * inv * g.y + bt.y,
                                 d2 * inv * g.z + bt.z,
                                 d3 * inv * g.w + bt.w);
}

// ---------------------------------------------------------------------------
extern "C" void kernel_launch(void* const* d_in, const int* in_sizes, int n_in,
                              void* d_out, int out_size) {
    (void)in_sizes; (void)n_in; (void)out_size;
    const float* mem   = (const float*)d_in[0];
    const float* dec   = (const float*)d_in[1];
    const float* qmask = (const float*)d_in[2];
    const float* Wk    = (const float*)d_in[3];
    const float* Wv    = (const float*)d_in[4];
    const float* Wq    = (const float*)d_in[5];
    const float* Wf    = (const float*)d_in[6];
    const float* bf    = (const float*)d_in[7];
    const float* gamma = (const float*)d_in[8];
    const float* beta  = (const float*)d_in[9];
    const void*  mask  = d_in[10];

    float* out  = (float*)d_out;
    float* attn = out + XSIZE;

    cudaFuncSetAttribute(projKQ_mma_kernel, cudaFuncAttributeMaxDynamicSharedMemorySize, SMEM2_TOT);
    cudaFuncSetAttribute(projV_mma_kernel,  cudaFuncAttributeMaxDynamicSharedMemorySize, SMEM1_TOT);
    cudaFuncSetAttribute(attn_fused_kernel, cudaFuncAttributeMaxDynamicSharedMemorySize, SMEM_ATTN);
    cudaFuncSetAttribute(pv_mma_kernel,     cudaFuncAttributeMaxDynamicSharedMemorySize, SMEM1_TOT);
    cudaFuncSetAttribute(final_mma_kernel,  cudaFuncAttributeMaxDynamicSharedMemorySize, SMEM2_TOT);

    detect_mask_kernel<<<1, 32>>>(mask);
    conv_hilo_kernel<<<8192, 256>>>(mem, 0, XSIZE / 4);
    conv_hilo_kernel<<<8192, 256>>>(dec, 1, XSIZE / 4);
    convT_kernel<<<dim3(32, 32), dim3(32, 8)>>>(Wk, 0, 1024, 1024);
    convT_kernel<<<dim3(32, 32), dim3(32, 8)>>>(Wv, 1, 1024, 1024);
    convT_kernel<<<dim3(32, 32), dim3(32, 8)>>>(Wq, 2, 1024, 1024);
    convT_kernel<<<dim3(32, 64), dim3(32, 8)>>>(Wf, 3, 2048, 1024);

    projKQ_mma_kernel<<<dim3(8, 64, 2), 256, SMEM2_TOT>>>();
    projV_mma_kernel<<<dim3(8, 64), 256, SMEM1_TOT>>>();
    transposeV_kernel<<<dim3(4, 32, 64), dim3(32, 8)>>>();
    attn_fused_kernel<<<dim3(32, 64), 256, SMEM_ATTN>>>(attn, qmask, mask);
    pv_mma_kernel<<<dim3(8, 64), 256, SMEM1_TOT>>>();
    final_mma_kernel<<<dim3(8, 64), 256, SMEM2_TOT>>>(dec, bf);
    ln_kernel<<<8192, 256>>>(gamma, beta, out);
}

// round 11
// speedup vs baseline: 1.4354x; 1.2815x over previous
#include <cuda_runtime.h>
#include <cuda_fp16.h>
#include <cstdint>
#include <math.h>

// ---------------------------------------------------------------------------
// Problem constants
// ---------------------------------------------------------------------------
#define NB 8
#define SQ 1024
#define SK 1024
#define DD 1024
#define NH 8
#define DH 128
#define HB (NH*NB)              // 64
#define XSIZE (NB*SQ*DD)        // 8388608
#define NEGV (-4294967295.0f)
#define SCALE 0.0883883476483184405f

// K32-chunk buffers (1-term kernels): 128 rows x 32 fp16, pitch 80B
#define ROWB 80
#define OP_BYTES (128*ROWB)       // 10240
#define BUF1_BYTES (2*OP_BYTES)   // 20480  (Ah,Bh)
#define SMEM1_TOT (3*BUF1_BYTES)  // 61440

// K64-chunk buffers (2-term kernels): 128 rows x 64 fp16, pitch 144B, 3 slots
#define ROWB2 144
#define OP2_BYTES (128*ROWB2)     // 18432
#define OFF2_AL (1*OP2_BYTES)
#define OFF2_BH (2*OP2_BYTES)
#define BUF2_BYTES (3*OP2_BYTES)  // 55296
#define SMEM2_TOT (2*BUF2_BYTES)  // 110592

// attn_fused smem layout (Kh only now)
#define ROWQ 272                  // 256B data + 16B skew
#define S_PITCH 1032              // fp32 words per S row (skewed)
#define SM_Q (32*S_PITCH*4)       // 132096
#define B_BUF (64*ROWQ)           // 17408 (Kh only)
#define SM_B (SM_Q + 2*32*ROWQ)   // 149504
#define SMEM_ATTN (SM_B + 2*B_BUF) // 184320

// ---------------------------------------------------------------------------
// Scratch (device globals — referenced ONLY from device code)
// ---------------------------------------------------------------------------
__device__ __half g_memh[NB*SK*DD], g_meml[NB*SK*DD];
__device__ __half g_dech[NB*SQ*DD], g_decl[NB*SQ*DD];
__device__ __half g_Wkt_h[DD*DD];
__device__ __half g_Wvt_h[DD*DD];
__device__ __half g_Wqt_h[DD*DD];
__device__ __half g_Wft_h[DD*2*DD];
__device__ __half g_Kh[HB*SK*DH];
__device__ __half g_Qh[HB*SQ*DH], g_Ql[HB*SQ*DH];
__device__ __half g_Vh[HB*SK*DH];          // [hb][s][d]
__device__ __half g_Vth[HB*DH*SK];         // [hb][d][s]
__device__ __half g_Ph[(size_t)HB*SQ*SK];
__device__ __half g_Oh[NB*SQ*DD];
__device__ float  g_X[NB*SQ*DD];
__device__ int    g_maskmode;

// ---------------------------------------------------------------------------
// Helpers
// ---------------------------------------------------------------------------
__device__ __forceinline__ uint32_t smem_to_u32(const void* p) {
    uint32_t a;
    asm("{ .reg .u64 t; cvta.to.shared.u64 t, %1; cvt.u32.u64 %0, t; }" : "=r"(a) : "l"(p));
    return a;
}

__device__ __forceinline__ void cp16(uint32_t dst, const void* src) {
    asm volatile("cp.async.cg.shared.global [%0], [%1], 16;" :: "r"(dst), "l"(src));
}
#define CP_COMMIT() asm volatile("cp.async.commit_group;" ::: "memory")
#define CP_WAIT(n)  asm volatile("cp.async.wait_group %0;" :: "n"(n) : "memory")

__device__ __forceinline__ void ldm_x4(uint32_t* r, uint32_t addr) {
    asm volatile("ldmatrix.sync.aligned.m8n8.x4.shared.b16 {%0,%1,%2,%3}, [%4];"
        : "=r"(r[0]), "=r"(r[1]), "=r"(r[2]), "=r"(r[3]) : "r"(addr));
}

__device__ __forceinline__ void mma16816(float* d, const uint32_t* a, const uint32_t* b) {
    asm volatile("mma.sync.aligned.m16n8k16.row.col.f32.f16.f16.f32 "
        "{%0,%1,%2,%3}, {%4,%5,%6,%7}, {%8,%9}, {%0,%1,%2,%3};"
        : "+f"(d[0]), "+f"(d[1]), "+f"(d[2]), "+f"(d[3])
        : "r"(a[0]), "r"(a[1]), "r"(a[2]), "r"(a[3]), "r"(b[0]), "r"(b[1]));
}

__device__ __forceinline__ void split_hilo(float v, __half& h, __half& l) {
    h = __float2half(v);
    l = __float2half(v - __half2float(h));
}
__device__ __forceinline__ uint32_t pack2h(float v0, float v1) {
    __half h0, l0, h1, l1;
    split_hilo(v0, h0, l0); split_hilo(v1, h1, l1);
    __half2 p = __halves2half2(h0, h1);
    return *reinterpret_cast<uint32_t*>(&p);
}
__device__ __forceinline__ uint32_t pack2l(float v0, float v1) {
    __half h0, l0, h1, l1;
    split_hilo(v0, h0, l0); split_hilo(v1, h1, l1);
    __half2 p = __halves2half2(l0, l1);
    return *reinterpret_cast<uint32_t*>(&p);
}

#define ACC_ZERO() do { \
    _Pragma("unroll") for (int _i = 0; _i < 2; _i++) \
    _Pragma("unroll") for (int _j = 0; _j < 8; _j++) \
    _Pragma("unroll") for (int _k = 0; _k < 4; _k++) acc[_i][_j][_k] = 0.f; \
} while (0)

// ---------------------------------------------------------------------------
// K32-chunk, 1-term building blocks (projV, pv)
// ---------------------------------------------------------------------------
__device__ __forceinline__ void load_chunk1(
    uint32_t sbuf, const __half* __restrict__ Ah,
    const __half* __restrict__ Bh, int lda, int ldb, int tid)
{
#pragma unroll
    for (int i = tid; i < 512; i += 256) {
        int row = i >> 2, ch = i & 3;
        uint32_t d = sbuf + row*ROWB + ch*16;
        cp16(d,            (const char*)Ah + (size_t)row * lda * 2 + ch*16);
        cp16(d + OP_BYTES, (const char*)Bh + (size_t)row * ldb * 2 + ch*16);
    }
}

__device__ __forceinline__ void compute_chunk1(uint32_t sbuf, int lane, int m0, int n0,
                                               float acc[2][8][4])
{
#pragma unroll
    for (int kk = 0; kk < 2; kk++) {
        uint32_t ah[2][4];
        int arow = m0 + (lane & 15);
        uint32_t abase = sbuf + kk*32 + ((lane >> 4) & 1)*16;
        ldm_x4(ah[0], abase + arow*ROWB);
        ldm_x4(ah[1], abase + (arow + 16)*ROWB);

        uint32_t bh[4][4];
        int brow = n0 + ((lane >> 4) << 3) + (lane & 7);
        uint32_t bko = ((lane >> 3) & 1) * 16 + kk*32;
#pragma unroll
        for (int nb = 0; nb < 4; nb++)
            ldm_x4(bh[nb], sbuf + OP_BYTES + (brow + nb*16)*ROWB + bko);
#pragma unroll
        for (int mi = 0; mi < 2; mi++)
#pragma unroll
            for (int ni = 0; ni < 8; ni++)
                mma16816(acc[mi][ni], ah[mi], &bh[ni >> 1][(ni & 1) * 2]);
    }
}

#define PIPELINE3(KC, BUFSZ, LOADC, COMPUTEC) do { \
    { LOADC(0, sb + 0*(BUFSZ)); } CP_COMMIT(); \
    { LOADC(1, sb + 1*(BUFSZ)); } CP_COMMIT(); \
    for (int c = 0; c < (KC); c++) { \
        if (c + 2 < (KC)) { LOADC((c + 2), sb + ((c + 2) % 3)*(BUFSZ)); } \
        CP_COMMIT(); \
        CP_WAIT(2); \
        __syncthreads(); \
        { COMPUTEC(c, sb + (c % 3)*(BUFSZ)); } \
        __syncthreads(); \
    } \
} while (0)

// ---------------------------------------------------------------------------
// K64-chunk building blocks (projKQ, final). TERMS=2: AhBh+AlBh; TERMS=1: AhBh.
// ---------------------------------------------------------------------------
template<int TERMS>
__device__ __forceinline__ void load_chunk64(
    uint32_t sbuf,
    const __half* __restrict__ Ah, const __half* __restrict__ Al,
    const __half* __restrict__ Bh, int lda, int ldb, int tid)
{
#pragma unroll
    for (int i = tid; i < 1024; i += 256) {
        int row = i >> 3, ch = i & 7;
        uint32_t d = sbuf + row*ROWB2 + ch*16;
        size_t ao = (size_t)row * lda * 2 + ch*16;
        size_t bo = (size_t)row * ldb * 2 + ch*16;
        cp16(d,           (const char*)Ah + ao);
        cp16(d + OFF2_BH, (const char*)Bh + bo);
        if (TERMS == 2)
            cp16(d + OFF2_AL, (const char*)Al + ao);
    }
}

template<int TERMS>
__device__ __forceinline__ void compute_chunk64(uint32_t sbuf, int lane, int m0, int n0,
                                                float acc[2][8][4])
{
#pragma unroll
    for (int kk = 0; kk < 4; kk++) {
        uint32_t ah[2][4], al[2][4];
        int arow = m0 + (lane & 15);
        uint32_t abase = sbuf + kk*32 + ((lane >> 4) & 1)*16;
        ldm_x4(ah[0], abase + arow*ROWB2);
        ldm_x4(ah[1], abase + (arow + 16)*ROWB2);
        if (TERMS == 2) {
            ldm_x4(al[0], abase + OFF2_AL + arow*ROWB2);
            ldm_x4(al[1], abase + OFF2_AL + (arow + 16)*ROWB2);
        }

        uint32_t bh[4][4];
        int brow = n0 + ((lane >> 4) << 3) + (lane & 7);
        uint32_t bko = ((lane >> 3) & 1) * 16 + kk*32;
#pragma unroll
        for (int nb = 0; nb < 4; nb++)
            ldm_x4(bh[nb], sbuf + OFF2_BH + (brow + nb*16)*ROWB2 + bko);
#pragma unroll
        for (int mi = 0; mi < 2; mi++)
#pragma unroll
            for (int ni = 0; ni < 8; ni++) {
                const uint32_t* BH = &bh[ni >> 1][(ni & 1) * 2];
                mma16816(acc[mi][ni], ah[mi], BH);
                if (TERMS == 2)
                    mma16816(acc[mi][ni], al[mi], BH);
            }
    }
}

#define PIPELINE2(KC, BUFSZ, LOADC, COMPUTEC) do { \
    { LOADC(0, sb); } CP_COMMIT(); \
    for (int c = 0; c < (KC); c++) { \
        if (c + 1 < (KC)) { \
            { LOADC((c + 1), sb + ((c + 1) & 1)*(BUFSZ)); } \
            CP_COMMIT(); \
            CP_WAIT(1); \
        } else CP_WAIT(0); \
        __syncthreads(); \
        { COMPUTEC(c, sb + (c & 1)*(BUFSZ)); } \
        __syncthreads(); \
    } \
} while (0)

// ---------------------------------------------------------------------------
// Mask dtype detection
// ---------------------------------------------------------------------------
__global__ void detect_mask_kernel(const void* __restrict__ mask) {
    int t = threadIdx.x;
    const int* pi = (const int*)mask;
    const float* pf = (const float*)mask;
    bool oki = true, okf = true;
    for (int i = t; i < 256; i += 32) {
        int v = pi[i];
        oki = oki && (v == 0 || v == 1);
        float f = pf[i];
        okf = okf && (f == 0.0f || f == 1.0f);
    }
    oki = __all_sync(0xFFFFFFFFu, oki);
    okf = __all_sync(0xFFFFFFFFu, okf);
    if (t == 0) g_maskmode = oki ? 0 : (okf ? 1 : 2);
}

// ---------------------------------------------------------------------------
// fp32 -> fp16 hi/lo. which=0 -> g_mem*, which=1 -> g_dec*
// ---------------------------------------------------------------------------
__global__ void conv_hilo_kernel(const float* __restrict__ src, int which, int n4) {
    __half* __restrict__ dh = which ? g_dech : g_memh;
    __half* __restrict__ dl = which ? g_decl : g_meml;
    int idx = blockIdx.x * blockDim.x + threadIdx.x;
    if (idx >= n4) return;
    float4 v = ((const float4*)src)[idx];
    uint2 hw, lw;
    hw.x = pack2h(v.x, v.y); hw.y = pack2h(v.z, v.w);
    lw.x = pack2l(v.x, v.y); lw.y = pack2l(v.z, v.w);
    ((uint2*)dh)[idx] = hw;
    ((uint2*)dl)[idx] = lw;
}

// ---------------------------------------------------------------------------
// W [K][N] fp32 -> Wt [N][K] fp16 (single). which: 0=Wk 1=Wv 2=Wq 3=Wf
// ---------------------------------------------------------------------------
__global__ void convT_kernel(const float* __restrict__ src, int which, int K, int N) {
    __half* dh;
    if (which == 0)      dh = g_Wkt_h;
    else if (which == 1) dh = g_Wvt_h;
    else if (which == 2) dh = g_Wqt_h;
    else                 dh = g_Wft_h;

    __shared__ float t[32][33];
    int n0 = blockIdx.x * 32, k0 = blockIdx.y * 32;
    int tx = threadIdx.x;
    for (int i = threadIdx.y; i < 32; i += 8)
        t[i][tx] = src[(size_t)(k0 + i) * N + n0 + tx];
    __syncthreads();
    for (int i = threadIdx.y; i < 32; i += 8) {
        size_t o = (size_t)(n0 + i) * K + k0 + tx;
        dh[o] = __float2half(t[tx][i]);
    }
}

// ---------------------------------------------------------------------------
// V [hb][1024][128] fp16 -> Vt [hb][128][1024] fp16 (16-bit move)
// ---------------------------------------------------------------------------
__global__ void transposeV_kernel() {
    __shared__ unsigned short t[32][33];
    int hb = blockIdx.z;
    int d0 = blockIdx.x * 32, s0 = blockIdx.y * 32;
    int tx = threadIdx.x;
    const unsigned short* src = (const unsigned short*)g_Vh + (size_t)hb * SK * DH;
    for (int i = threadIdx.y; i < 32; i += 8)
        t[i][tx] = src[(size_t)(s0 + i) * 128 + d0 + tx];
    __syncthreads();
    for (int i = threadIdx.y; i < 32; i += 8) {
        size_t o = (size_t)hb * DH * SK + (size_t)(d0 + i) * 1024 + s0 + tx;
        ((unsigned short*)g_Vth)[o] = t[tx][i];
    }
}

// ---------------------------------------------------------------------------
// Projection GEMM K/Q (HMMA, 2-term fp16, K64): z=0 K (h only), z=1 Q (h+l).
// ---------------------------------------------------------------------------
__global__ __launch_bounds__(256, 2) void projKQ_mma_kernel() {
    extern __shared__ char smem[];
    uint32_t sb = smem_to_u32(smem);
    int tid = threadIdx.x, lane = tid & 31, w = tid >> 5;
    int m0 = (w & 3) * 32, n0 = (w >> 2) * 64;
    int bx = blockIdx.x, by = blockIdx.y, z = blockIdx.z;

    const __half* Ah = ((z == 1) ? g_dech : g_memh) + (size_t)by * 128 * 1024;
    const __half* Al = ((z == 1) ? g_decl : g_meml) + (size_t)by * 128 * 1024;
    const __half* Bh = ((z == 0) ? g_Wkt_h : g_Wqt_h) + (size_t)bx * 128 * 1024;

    float acc[2][8][4];
    ACC_ZERO();

#define LOADC(cc, buf) load_chunk64<2>((buf), Ah + (cc)*64, Al + (cc)*64, Bh + (cc)*64, 1024, 1024, tid)
#define COMPUTEC(cc, buf) compute_chunk64<2>((buf), lane, m0, n0, acc)
    PIPELINE2(16, BUF2_BYTES, LOADC, COMPUTEC);
#undef LOADC
#undef COMPUTEC

#pragma unroll
    for (int mi = 0; mi < 2; mi++)
#pragma unroll
        for (int ni = 0; ni < 8; ni++) {
            int cc = n0 + ni * 8 + (lane & 3) * 2;
#pragma unroll
            for (int half = 0; half < 2; half++) {
                int rr = by * 128 + m0 + mi * 16 + (lane >> 2) + half * 8;
                float d0 = acc[mi][ni][half * 2], d1 = acc[mi][ni][half * 2 + 1];
                int bb = rr >> 10, ss = rr & 1023;
                size_t base = (((size_t)(bx * 8 + bb)) * 1024 + ss) * 128 + cc;
                if (z == 0) {
                    *(uint32_t*)(g_Kh + base) = pack2h(d0, d1);
                } else {
                    *(uint32_t*)(g_Qh + base) = pack2h(d0, d1);
                    *(uint32_t*)(g_Ql + base) = pack2l(d0, d1);
                }
            }
        }
}

// ---------------------------------------------------------------------------
// Projection GEMM V (HMMA, 1-term fp16, K32, compact smem)
// ---------------------------------------------------------------------------
__global__ __launch_bounds__(256, 2) void projV_mma_kernel() {
    extern __shared__ char smem[];
    uint32_t sb = smem_to_u32(smem);
    int tid = threadIdx.x, lane = tid & 31, w = tid >> 5;
    int m0 = (w & 3) * 32, n0 = (w >> 2) * 64;
    int bx = blockIdx.x, by = blockIdx.y;

    const __half* Ah = g_memh + (size_t)by * 128 * 1024;
    const __half* Bh = g_Wvt_h + (size_t)bx * 128 * 1024;

    float acc[2][8][4];
    ACC_ZERO();

#define LOADC(cc, buf) load_chunk1((buf), Ah + (cc)*32, Bh + (cc)*32, 1024, 1024, tid)
#define COMPUTEC(cc, buf) compute_chunk1((buf), lane, m0, n0, acc)
    PIPELINE3(32, BUF1_BYTES, LOADC, COMPUTEC);
#undef LOADC
#undef COMPUTEC

#pragma unroll
    for (int mi = 0; mi < 2; mi++)
#pragma unroll
        for (int ni = 0; ni < 8; ni++) {
            int cc = n0 + ni * 8 + (lane & 3) * 2;
#pragma unroll
            for (int half = 0; half < 2; half++) {
                int rr = by * 128 + m0 + mi * 16 + (lane >> 2) + half * 8;
                float d0 = acc[mi][ni][half * 2], d1 = acc[mi][ni][half * 2 + 1];
                int bb = rr >> 10, ss = rr & 1023;
                size_t base = (((size_t)(bx * 8 + bb)) * 1024 + ss) * 128 + cc;
                *(uint32_t*)(g_Vh + base) = pack2h(d0, d1);
            }
        }
}

// ---------------------------------------------------------------------------
// FUSED scores+softmax: one CTA = 32 query rows x 1024 keys.
// 2-term scores: (Qh+Ql)·Kh. S in smem; writes P fp32 + Ph fp16.
// ---------------------------------------------------------------------------
__global__ __launch_bounds__(256, 1) void attn_fused_kernel(
    float* __restrict__ attn, const float* __restrict__ qmask,
    const void* __restrict__ mask)
{
    extern __shared__ char smem[];
    uint32_t sb = smem_to_u32(smem);
    float* Ss = (float*)smem;
    int tid = threadIdx.x, lane = tid & 31, w = tid >> 5;
    const int wm = w >> 2;
    const int wn = w & 3;
    int blk = blockIdx.x;
    int y = blockIdx.y;
    int h = y & 7, b = y >> 3;
    int hb = h * 8 + b;
    int q0 = blk * 32;

    const char* Qh = (const char*)(g_Qh + ((size_t)hb * 1024 + q0) * 128);
    const char* Ql = (const char*)(g_Ql + ((size_t)hb * 1024 + q0) * 128);
    const char* Kh = (const char*)(g_Kh + (size_t)hb * 1024 * 128);

#pragma unroll
    for (int i = tid; i < 512; i += 256) {
        int row = i >> 4, ch = i & 15;
        uint32_t d = sb + SM_Q + row * ROWQ + ch * 16;
        size_t o = (size_t)row * 256 + ch * 16;
        cp16(d, Qh + o);
        cp16(d + 32 * ROWQ, Ql + o);
    }
    CP_COMMIT();

#pragma unroll
    for (int t = 0; t < 2; t++) {
        uint32_t bbuf = sb + SM_B + t * B_BUF;
#pragma unroll
        for (int i = tid; i < 1024; i += 256) {
            int row = i >> 4, ch = i & 15;
            cp16(bbuf + row * ROWQ + ch * 16,
                 Kh + (size_t)t * 64 * 256 + (size_t)row * 256 + ch * 16);
        }
        CP_COMMIT();
    }

    CP_WAIT(2);
    __syncthreads();
    uint32_t ah_reg[8][4], al_reg[8][4];
    {
        uint32_t abase = sb + SM_Q + (uint32_t)(wm * 16 + (lane & 15)) * ROWQ
                         + ((lane >> 4) & 1) * 16;
#pragma unroll
        for (int kk = 0; kk < 8; kk++) {
            ldm_x4(ah_reg[kk], abase + kk * 32);
            ldm_x4(al_reg[kk], abase + 32 * ROWQ + kk * 32);
        }
    }

    const int gid = lane >> 2, tig = lane & 3;
    for (int t = 0; t < 16; t++) {
        CP_WAIT(1);
        __syncthreads();
        uint32_t bbuf = sb + SM_B + (t & 1) * B_BUF;
        float acc[2][4];
#pragma unroll
        for (int ni = 0; ni < 2; ni++)
#pragma unroll
            for (int k = 0; k < 4; k++) acc[ni][k] = 0.f;

        uint32_t bbase = bbuf + (uint32_t)(wn * 16 + ((lane >> 4) << 3) + (lane & 7)) * ROWQ
                         + ((lane >> 3) & 1) * 16;
#pragma unroll
        for (int kk = 0; kk < 8; kk++) {
            uint32_t bh[4];
            ldm_x4(bh, bbase + kk * 32);
#pragma unroll
            for (int ni = 0; ni < 2; ni++) {
                mma16816(acc[ni], ah_reg[kk], &bh[ni * 2]);
                mma16816(acc[ni], al_reg[kk], &bh[ni * 2]);
            }
        }
        int col0 = t * 64 + wn * 16;
#pragma unroll
        for (int ni = 0; ni < 2; ni++)
#pragma unroll
            for (int half = 0; half < 2; half++) {
                int row = wm * 16 + gid + half * 8;
                int col = col0 + ni * 8 + tig * 2;
                *(float2*)(Ss + row * S_PITCH + col) =
                    make_float2(acc[ni][half * 2] * SCALE, acc[ni][half * 2 + 1] * SCALE);
            }
        __syncthreads();
        if (t + 2 < 16) {
            uint32_t nbuf = sb + SM_B + (t & 1) * B_BUF;
#pragma unroll
            for (int i = tid; i < 1024; i += 256) {
                int row = i >> 4, ch = i & 15;
                cp16(nbuf + row * ROWQ + ch * 16,
                     Kh + (size_t)(t + 2) * 64 * 256 + (size_t)row * 256 + ch * 16);
            }
        }
        CP_COMMIT();
    }
    __syncthreads();

    const int mode = g_maskmode;
#pragma unroll 1
    for (int j = 0; j < 4; j++) {
        int r = w * 4 + j;
        int q = q0 + r;
        const float* srow = Ss + r * S_PITCH;
        const size_t mrow = ((size_t)b * 1024 + q) * 1024;

        float v[32];
        float mx = -3.4e38f;
#pragma unroll
        for (int c8 = 0; c8 < 8; c8++) {
            int col = c8 * 128 + lane * 4;
            float4 x = *(const float4*)(srow + col);
            int m0i, m1i, m2i, m3i;
            if (mode == 0) {
                int4 mv = *(const int4*)((const int*)mask + mrow + col);
                m0i = mv.x; m1i = mv.y; m2i = mv.z; m3i = mv.w;
            } else if (mode == 1) {
                float4 mv = *(const float4*)((const float*)mask + mrow + col);
                m0i = (mv.x != 0.f); m1i = (mv.y != 0.f); m2i = (mv.z != 0.f); m3i = (mv.w != 0.f);
            } else {
                uchar4 mv = *(const uchar4*)((const unsigned char*)mask + mrow + col);
                m0i = mv.x; m1i = mv.y; m2i = mv.z; m3i = mv.w;
            }
            v[c8*4+0] = m0i ? NEGV : x.x;
            v[c8*4+1] = m1i ? NEGV : x.y;
            v[c8*4+2] = m2i ? NEGV : x.z;
            v[c8*4+3] = m3i ? NEGV : x.w;
            mx = fmaxf(mx, fmaxf(fmaxf(v[c8*4+0], v[c8*4+1]), fmaxf(v[c8*4+2], v[c8*4+3])));
        }
#pragma unroll
        for (int s = 16; s > 0; s >>= 1)
            mx = fmaxf(mx, __shfl_xor_sync(0xFFFFFFFFu, mx, s));

        float sum = 0.f;
#pragma unroll
        for (int i = 0; i < 32; i++) {
            v[i] = expf(v[i] - mx);
            sum += v[i];
        }
#pragma unroll
        for (int s = 16; s > 0; s >>= 1)
            sum += __shfl_xor_sync(0xFFFFFFFFu, sum, s);

        float inv = qmask[b * 1024 + q] / sum;
        float* prow = attn + ((size_t)hb * 1024 + q) * 1024;
        __half* phrow = g_Ph + ((size_t)hb * 1024 + q) * 1024;
#pragma unroll
        for (int c8 = 0; c8 < 8; c8++) {
            int col = c8 * 128 + lane * 4;
            float p0 = v[c8*4+0] * inv, p1 = v[c8*4+1] * inv;
            float p2 = v[c8*4+2] * inv, p3 = v[c8*4+3] * inv;
            *(float4*)(prow + col) = make_float4(p0, p1, p2, p3);
            uint2 hw;
            hw.x = pack2h(p0, p1); hw.y = pack2h(p2, p3);
            *(uint2*)(phrow + col) = hw;
        }
    }
}

// ---------------------------------------------------------------------------
// PV GEMM (HMMA, 1-term fp16, K32, compact smem): O = Ph @ Vt
// ---------------------------------------------------------------------------
__global__ __launch_bounds__(256, 2) void pv_mma_kernel() {
    extern __shared__ char smem[];
    uint32_t sb = smem_to_u32(smem);
    int tid = threadIdx.x, lane = tid & 31, w = tid >> 5;
    int m0 = (w & 3) * 32, n0 = (w >> 2) * 64;
    int bx = blockIdx.x, hb = blockIdx.y;

    const __half* Ah = g_Ph + ((size_t)hb * 1024 + bx * 128) * 1024;
    const __half* Bh = g_Vth + (size_t)hb * DH * SK;

    float acc[2][8][4];
    ACC_ZERO();

#define LOADC(cc, buf) load_chunk1((buf), Ah + (cc)*32, Bh + (cc)*32, 1024, 1024, tid)
#define COMPUTEC(cc, buf) compute_chunk1((buf), lane, m0, n0, acc)
    PIPELINE3(32, BUF1_BYTES, LOADC, COMPUTEC);
#undef LOADC
#undef COMPUTEC

    const int b = hb & 7, h = hb >> 3;
#pragma unroll
    for (int mi = 0; mi < 2; mi++)
#pragma unroll
        for (int ni = 0; ni < 8; ni++) {
            int cc = n0 + ni * 8 + (lane & 3) * 2;
#pragma unroll
            for (int half = 0; half < 2; half++) {
                int q = bx * 128 + m0 + mi * 16 + (lane >> 2) + half * 8;
                float d0 = acc[mi][ni][half * 2], d1 = acc[mi][ni][half * 2 + 1];
                size_t base = ((size_t)b * 1024 + q) * 1024 + h * 128 + cc;
                *(uint32_t*)(g_Oh + base) = pack2h(d0, d1);
            }
        }
}

// ---------------------------------------------------------------------------
// Final GEMM (HMMA, K64): X = [dec | O] @ Wf + bf + dec  (K = 2048)
// chunks 0..15: dec-half 2-term; chunks 16..31: O-half 1-term.
// ---------------------------------------------------------------------------
__global__ __launch_bounds__(256, 2) void final_mma_kernel(
    const float* __restrict__ dec, const float* __restrict__ bf) {
    extern __shared__ char smem[];
    uint32_t sb = smem_to_u32(smem);
    int tid = threadIdx.x, lane = tid & 31, w = tid >> 5;
    int m0 = (w & 3) * 32, n0 = (w >> 2) * 64;
    int bx = blockIdx.x, by = blockIdx.y;
    const size_t arow0 = (size_t)by * 128;

    const __half* Bh = g_Wft_h + (size_t)bx * 128 * 2048;

    float acc[2][8][4];
    ACC_ZERO();

#define LOADC(cc, buf) do { \
    int _k0 = (cc) * 64; \
    if (_k0 < 1024) \
        load_chunk64<2>((buf), g_dech + arow0*1024 + _k0, g_decl + arow0*1024 + _k0, \
                        Bh + _k0, 1024, 2048, tid); \
    else \
        load_chunk64<1>((buf), g_Oh + arow0*1024 + (_k0 - 1024), nullptr, \
                        Bh + _k0, 1024, 2048, tid); \
} while (0)
#define COMPUTEC(cc, buf) do { \
    if ((cc) < 16) compute_chunk64<2>((buf), lane, m0, n0, acc); \
    else           compute_chunk64<1>((buf), lane, m0, n0, acc); \
} while (0)
    PIPELINE2(32, BUF2_BYTES, LOADC, COMPUTEC);
#undef LOADC
#undef COMPUTEC

#pragma unroll
    for (int mi = 0; mi < 2; mi++)
#pragma unroll
        for (int ni = 0; ni < 8; ni++) {
            int cc = bx * 128 + n0 + ni * 8 + (lane & 3) * 2;
            float2 bv = *(const float2*)(bf + cc);
#pragma unroll
            for (int half = 0; half < 2; half++) {
                int rr = by * 128 + m0 + mi * 16 + (lane >> 2) + half * 8;
                float d0 = acc[mi][ni][half * 2], d1 = acc[mi][ni][half * 2 + 1];
                float2 dv = *(const float2*)(dec + (size_t)rr * 1024 + cc);
                *(float2*)(g_X + (size_t)rr * 1024 + cc) =
                    make_float2(d0 + bv.x + dv.x, d1 + bv.y + dv.y);
            }
        }
}

// ---------------------------------------------------------------------------
// LayerNorm
// ---------------------------------------------------------------------------
__global__ __launch_bounds__(256) void ln_kernel(
    const float* __restrict__ gamma, const float* __restrict__ beta,
    float* __restrict__ out) {
    const int rowid = blockIdx.x;
    const int tid = threadIdx.x;
    const float* rp = g_X + (size_t)rowid * 1024;

    float4 x = *(const float4*)(rp + tid * 4);
    __shared__ float red[256];
    red[tid] = x.x + x.y + x.z + x.w;
    __syncthreads();
#pragma unroll
    for (int s = 128; s > 0; s >>= 1) {
        if (tid < s) red[tid] += red[tid + s];
        __syncthreads();
    }
    float mean = red[0] * (1.0f / 1024.0f);
    __syncthreads();

    float d0 = x.x - mean, d1 = x.y - mean, d2 = x.z - mean, d3 = x.w - mean;
    red[tid] = d0 * d0 + d1 * d1 + d2 * d2 + d3 * d3;
    __syncthreads();
#pragma unroll
    for (int s = 128; s > 0; s >>= 1) {
        if (tid < s) red[tid] += red[tid + s];
        __syncthreads();
    }
    float var = red[0] * (1.0f / 1024.0f);
    float inv = rsqrtf(var + 1e-5f);

    float4 g = *(const float4*)(gamma + tid * 4);
    float4 bt = *(const float4*)(beta + tid * 4);
    float* optr = out + (size_t)rowid * 1024 + tid * 4;
    *(float4*)optr = make_float4(d0 * inv * g.x + bt.x,
                                 d1 * inv * g.y + bt.y,
                                 d2 * inv * g.z + bt.z,
                                 d3 * inv * g.w + bt.w);
}

// ---------------------------------------------------------------------------
extern "C" void kernel_launch(void* const* d_in, const int* in_sizes, int n_in,
                              void* d_out, int out_size) {
    (void)in_sizes; (void)n_in; (void)out_size;
    const float* mem   = (const float*)d_in[0];
    const float* dec   = (const float*)d_in[1];
    const float* qmask = (const float*)d_in[2];
    const float* Wk    = (const float*)d_in[3];
    const float* Wv    = (const float*)d_in[4];
    const float* Wq    = (const float*)d_in[5];
    const float* Wf    = (const float*)d_in[6];
    const float* bf    = (const float*)d_in[7];
    const float* gamma = (const float*)d_in[8];
    const float* beta  = (const float*)d_in[9];
    const void*  mask  = d_in[10];

    float* out  = (float*)d_out;
    float* attn = out + XSIZE;

    cudaFuncSetAttribute(projKQ_mma_kernel, cudaFuncAttributeMaxDynamicSharedMemorySize, SMEM2_TOT);
    cudaFuncSetAttribute(projV_mma_kernel,  cudaFuncAttributeMaxDynamicSharedMemorySize, SMEM1_TOT);
    cudaFuncSetAttribute(attn_fused_kernel, cudaFuncAttributeMaxDynamicSharedMemorySize, SMEM_ATTN);
    cudaFuncSetAttribute(pv_mma_kernel,     cudaFuncAttributeMaxDynamicSharedMemorySize, SMEM1_TOT);
    cudaFuncSetAttribute(final_mma_kernel,  cudaFuncAttributeMaxDynamicSharedMemorySize, SMEM2_TOT);

    detect_mask_kernel<<<1, 32>>>(mask);
    conv_hilo_kernel<<<8192, 256>>>(mem, 0, XSIZE / 4);
    conv_hilo_kernel<<<8192, 256>>>(dec, 1, XSIZE / 4);
    convT_kernel<<<dim3(32, 32), dim3(32, 8)>>>(Wk, 0, 1024, 1024);
    convT_kernel<<<dim3(32, 32), dim3(32, 8)>>>(Wv, 1, 1024, 1024);
    convT_kernel<<<dim3(32, 32), dim3(32, 8)>>>(Wq, 2, 1024, 1024);
    convT_kernel<<<dim3(32, 64), dim3(32, 8)>>>(Wf, 3, 2048, 1024);

    projKQ_mma_kernel<<<dim3(8, 64, 2), 256, SMEM2_TOT>>>();
    projV_mma_kernel<<<dim3(8, 64), 256, SMEM1_TOT>>>();
    transposeV_kernel<<<dim3(4, 32, 64), dim3(32, 8)>>>();
    attn_fused_kernel<<<dim3(32, 64), 256, SMEM_ATTN>>>(attn, qmask, mask);
    pv_mma_kernel<<<dim3(8, 64), 256, SMEM1_TOT>>>();
    final_mma_kernel<<<dim3(8, 64), 256, SMEM2_TOT>>>(dec, bf);
    ln_kernel<<<8192, 256>>>(gamma, beta, out);
}

// round 12
// speedup vs baseline: 1.7161x; 1.1956x over previous
#include <cuda_runtime.h>
#include <cuda_fp16.h>
#include <cstdint>
#include <math.h>

// ---------------------------------------------------------------------------
// Problem constants
// ---------------------------------------------------------------------------
#define NB 8
#define SQ 1024
#define SK 1024
#define DD 1024
#define NH 8
#define DH 128
#define HB (NH*NB)              // 64
#define XSIZE (NB*SQ*DD)        // 8388608
#define NEGV (-4294967295.0f)
#define SCALE 0.0883883476483184405f

// K32-chunk buffers (pv): 128 rows x 32 fp16, pitch 80B
#define ROWB 80
#define OP_BYTES (128*ROWB)       // 10240
#define BUF1_BYTES (2*OP_BYTES)   // 20480  (Ah,Bh)
#define SMEM1_TOT (3*BUF1_BYTES)  // 61440

// K64-chunk 1-term buffers (proj, final): 128 rows x 64 fp16, pitch 144B
#define ROWB2 144
#define OP2_BYTES (128*ROWB2)     // 18432
#define BUF2_BYTES (2*OP2_BYTES)  // 36864  (Ah,Bh)
#define SMEM2_TOT (2*BUF2_BYTES)  // 73728

// attn_fused smem layout (Qh, Kh single only)
#define ROWQ 272                  // 256B data + 16B skew
#define S_PITCH 1032              // fp32 words per S row (skewed)
#define SM_Q (32*S_PITCH*4)       // 132096
#define SM_B (SM_Q + 32*ROWQ)     // 140800
#define B_BUF (64*ROWQ)           // 17408
#define SMEM_ATTN (SM_B + 2*B_BUF) // 175616

// ---------------------------------------------------------------------------
// Scratch (device globals — referenced ONLY from device code)
// ---------------------------------------------------------------------------
__device__ __half g_memh[NB*SK*DD];
__device__ __half g_dech[NB*SQ*DD];
__device__ __half g_Wkt_h[DD*DD];
__device__ __half g_Wvt_h[DD*DD];
__device__ __half g_Wqt_h[DD*DD];
__device__ __half g_Wft_h[DD*2*DD];
__device__ __half g_Kh[HB*SK*DH];
__device__ __half g_Qh[HB*SQ*DH];
__device__ __half g_Vh[HB*SK*DH];          // [hb][s][d]
__device__ __half g_Vth[HB*DH*SK];         // [hb][d][s]
__device__ __half g_Ph[(size_t)HB*SQ*SK];
__device__ __half g_Oh[NB*SQ*DD];
__device__ float  g_X[NB*SQ*DD];
__device__ int    g_maskmode;

// ---------------------------------------------------------------------------
// Helpers
// ---------------------------------------------------------------------------
__device__ __forceinline__ uint32_t smem_to_u32(const void* p) {
    uint32_t a;
    asm("{ .reg .u64 t; cvta.to.shared.u64 t, %1; cvt.u32.u64 %0, t; }" : "=r"(a) : "l"(p));
    return a;
}

__device__ __forceinline__ void cp16(uint32_t dst, const void* src) {
    asm volatile("cp.async.cg.shared.global [%0], [%1], 16;" :: "r"(dst), "l"(src));
}
#define CP_COMMIT() asm volatile("cp.async.commit_group;" ::: "memory")
#define CP_WAIT(n)  asm volatile("cp.async.wait_group %0;" :: "n"(n) : "memory")

__device__ __forceinline__ void ldm_x4(uint32_t* r, uint32_t addr) {
    asm volatile("ldmatrix.sync.aligned.m8n8.x4.shared.b16 {%0,%1,%2,%3}, [%4];"
        : "=r"(r[0]), "=r"(r[1]), "=r"(r[2]), "=r"(r[3]) : "r"(addr));
}

__device__ __forceinline__ void mma16816(float* d, const uint32_t* a, const uint32_t* b) {
    asm volatile("mma.sync.aligned.m16n8k16.row.col.f32.f16.f16.f32 "
        "{%0,%1,%2,%3}, {%4,%5,%6,%7}, {%8,%9}, {%0,%1,%2,%3};"
        : "+f"(d[0]), "+f"(d[1]), "+f"(d[2]), "+f"(d[3])
        : "r"(a[0]), "r"(a[1]), "r"(a[2]), "r"(a[3]), "r"(b[0]), "r"(b[1]));
}

__device__ __forceinline__ uint32_t pack2h(float v0, float v1) {
    __half2 p = __halves2half2(__float2half(v0), __float2half(v1));
    return *reinterpret_cast<uint32_t*>(&p);
}

#define ACC_ZERO() do { \
    _Pragma("unroll") for (int _i = 0; _i < 2; _i++) \
    _Pragma("unroll") for (int _j = 0; _j < 8; _j++) \
    _Pragma("unroll") for (int _k = 0; _k < 4; _k++) acc[_i][_j][_k] = 0.f; \
} while (0)

// ---------------------------------------------------------------------------
// K32-chunk 1-term building blocks (pv)
// ---------------------------------------------------------------------------
__device__ __forceinline__ void load_chunk1(
    uint32_t sbuf, const __half* __restrict__ Ah,
    const __half* __restrict__ Bh, int lda, int ldb, int tid)
{
#pragma unroll
    for (int i = tid; i < 512; i += 256) {
        int row = i >> 2, ch = i & 3;
        uint32_t d = sbuf + row*ROWB + ch*16;
        cp16(d,            (const char*)Ah + (size_t)row * lda * 2 + ch*16);
        cp16(d + OP_BYTES, (const char*)Bh + (size_t)row * ldb * 2 + ch*16);
    }
}

__device__ __forceinline__ void compute_chunk1(uint32_t sbuf, int lane, int m0, int n0,
                                               float acc[2][8][4])
{
#pragma unroll
    for (int kk = 0; kk < 2; kk++) {
        uint32_t ah[2][4];
        int arow = m0 + (lane & 15);
        uint32_t abase = sbuf + kk*32 + ((lane >> 4) & 1)*16;
        ldm_x4(ah[0], abase + arow*ROWB);
        ldm_x4(ah[1], abase + (arow + 16)*ROWB);

        uint32_t bh[4][4];
        int brow = n0 + ((lane >> 4) << 3) + (lane & 7);
        uint32_t bko = ((lane >> 3) & 1) * 16 + kk*32;
#pragma unroll
        for (int nb = 0; nb < 4; nb++)
            ldm_x4(bh[nb], sbuf + OP_BYTES + (brow + nb*16)*ROWB + bko);
#pragma unroll
        for (int mi = 0; mi < 2; mi++)
#pragma unroll
            for (int ni = 0; ni < 8; ni++)
                mma16816(acc[mi][ni], ah[mi], &bh[ni >> 1][(ni & 1) * 2]);
    }
}

#define PIPELINE3(KC, BUFSZ, LOADC, COMPUTEC) do { \
    { LOADC(0, sb + 0*(BUFSZ)); } CP_COMMIT(); \
    { LOADC(1, sb + 1*(BUFSZ)); } CP_COMMIT(); \
    for (int c = 0; c < (KC); c++) { \
        if (c + 2 < (KC)) { LOADC((c + 2), sb + ((c + 2) % 3)*(BUFSZ)); } \
        CP_COMMIT(); \
        CP_WAIT(2); \
        __syncthreads(); \
        { COMPUTEC(c, sb + (c % 3)*(BUFSZ)); } \
        __syncthreads(); \
    } \
} while (0)

// ---------------------------------------------------------------------------
// K64-chunk 1-term building blocks (proj, final)
// ---------------------------------------------------------------------------
__device__ __forceinline__ void load_chunk64(
    uint32_t sbuf, const __half* __restrict__ Ah,
    const __half* __restrict__ Bh, int lda, int ldb, int tid)
{
#pragma unroll
    for (int i = tid; i < 1024; i += 256) {
        int row = i >> 3, ch = i & 7;
        uint32_t d = sbuf + row*ROWB2 + ch*16;
        cp16(d,             (const char*)Ah + (size_t)row * lda * 2 + ch*16);
        cp16(d + OP2_BYTES, (const char*)Bh + (size_t)row * ldb * 2 + ch*16);
    }
}

__device__ __forceinline__ void compute_chunk64(uint32_t sbuf, int lane, int m0, int n0,
                                                float acc[2][8][4])
{
#pragma unroll
    for (int kk = 0; kk < 4; kk++) {
        uint32_t ah[2][4];
        int arow = m0 + (lane & 15);
        uint32_t abase = sbuf + kk*32 + ((lane >> 4) & 1)*16;
        ldm_x4(ah[0], abase + arow*ROWB2);
        ldm_x4(ah[1], abase + (arow + 16)*ROWB2);

        uint32_t bh[4][4];
        int brow = n0 + ((lane >> 4) << 3) + (lane & 7);
        uint32_t bko = ((lane >> 3) & 1) * 16 + kk*32;
#pragma unroll
        for (int nb = 0; nb < 4; nb++)
            ldm_x4(bh[nb], sbuf + OP2_BYTES + (brow + nb*16)*ROWB2 + bko);
#pragma unroll
        for (int mi = 0; mi < 2; mi++)
#pragma unroll
            for (int ni = 0; ni < 8; ni++)
                mma16816(acc[mi][ni], ah[mi], &bh[ni >> 1][(ni & 1) * 2]);
    }
}

#define PIPELINE2(KC, BUFSZ, LOADC, COMPUTEC) do { \
    { LOADC(0, sb); } CP_COMMIT(); \
    for (int c = 0; c < (KC); c++) { \
        if (c + 1 < (KC)) { \
            { LOADC((c + 1), sb + ((c + 1) & 1)*(BUFSZ)); } \
            CP_COMMIT(); \
            CP_WAIT(1); \
        } else CP_WAIT(0); \
        __syncthreads(); \
        { COMPUTEC(c, sb + (c & 1)*(BUFSZ)); } \
        __syncthreads(); \
    } \
} while (0)

// ---------------------------------------------------------------------------
// Mask dtype detection
// ---------------------------------------------------------------------------
__global__ void detect_mask_kernel(const void* __restrict__ mask) {
    int t = threadIdx.x;
    const int* pi = (const int*)mask;
    const float* pf = (const float*)mask;
    bool oki = true, okf = true;
    for (int i = t; i < 256; i += 32) {
        int v = pi[i];
        oki = oki && (v == 0 || v == 1);
        float f = pf[i];
        okf = okf && (f == 0.0f || f == 1.0f);
    }
    oki = __all_sync(0xFFFFFFFFu, oki);
    okf = __all_sync(0xFFFFFFFFu, okf);
    if (t == 0) g_maskmode = oki ? 0 : (okf ? 1 : 2);
}

// ---------------------------------------------------------------------------
// fp32 -> fp16 single. which=0 -> g_memh, which=1 -> g_dech
// ---------------------------------------------------------------------------
__global__ void conv_h_kernel(const float* __restrict__ src, int which, int n4) {
    __half* __restrict__ dh = which ? g_dech : g_memh;
    int idx = blockIdx.x * blockDim.x + threadIdx.x;
    if (idx >= n4) return;
    float4 v = ((const float4*)src)[idx];
    uint2 hw;
    hw.x = pack2h(v.x, v.y); hw.y = pack2h(v.z, v.w);
    ((uint2*)dh)[idx] = hw;
}

// ---------------------------------------------------------------------------
// W [K][N] fp32 -> Wt [N][K] fp16. which: 0=Wk 1=Wv 2=Wq 3=Wf
// ---------------------------------------------------------------------------
__global__ void convT_kernel(const float* __restrict__ src, int which, int K, int N) {
    __half* dh;
    if (which == 0)      dh = g_Wkt_h;
    else if (which == 1) dh = g_Wvt_h;
    else if (which == 2) dh = g_Wqt_h;
    else                 dh = g_Wft_h;

    __shared__ float t[32][33];
    int n0 = blockIdx.x * 32, k0 = blockIdx.y * 32;
    int tx = threadIdx.x;
    for (int i = threadIdx.y; i < 32; i += 8)
        t[i][tx] = src[(size_t)(k0 + i) * N + n0 + tx];
    __syncthreads();
    for (int i = threadIdx.y; i < 32; i += 8) {
        size_t o = (size_t)(n0 + i) * K + k0 + tx;
        dh[o] = __float2half(t[tx][i]);
    }
}

// ---------------------------------------------------------------------------
// V [hb][1024][128] fp16 -> Vt [hb][128][1024] fp16
// ---------------------------------------------------------------------------
__global__ void transposeV_kernel() {
    __shared__ unsigned short t[32][33];
    int hb = blockIdx.z;
    int d0 = blockIdx.x * 32, s0 = blockIdx.y * 32;
    int tx = threadIdx.x;
    const unsigned short* src = (const unsigned short*)g_Vh + (size_t)hb * SK * DH;
    for (int i = threadIdx.y; i < 32; i += 8)
        t[i][tx] = src[(size_t)(s0 + i) * 128 + d0 + tx];
    __syncthreads();
    for (int i = threadIdx.y; i < 32; i += 8) {
        size_t o = (size_t)hb * DH * SK + (size_t)(d0 + i) * 1024 + s0 + tx;
        ((unsigned short*)g_Vth)[o] = t[tx][i];
    }
}

// ---------------------------------------------------------------------------
// Projection GEMM (HMMA, 1-term fp16, K64): z=0 K, z=1 V, z=2 Q. Head-split.
// ---------------------------------------------------------------------------
__global__ __launch_bounds__(256, 2) void proj_mma_kernel() {
    extern __shared__ char smem[];
    uint32_t sb = smem_to_u32(smem);
    int tid = threadIdx.x, lane = tid & 31, w = tid >> 5;
    int m0 = (w & 3) * 32, n0 = (w >> 2) * 64;
    int bx = blockIdx.x, by = blockIdx.y, z = blockIdx.z;

    const __half* Ah = ((z == 2) ? g_dech : g_memh) + (size_t)by * 128 * 1024;
    const __half* Bh = ((z == 0) ? g_Wkt_h : ((z == 1) ? g_Wvt_h : g_Wqt_h))
                       + (size_t)bx * 128 * 1024;

    float acc[2][8][4];
    ACC_ZERO();

#define LOADC(cc, buf) load_chunk64((buf), Ah + (cc)*64, Bh + (cc)*64, 1024, 1024, tid)
#define COMPUTEC(cc, buf) compute_chunk64((buf), lane, m0, n0, acc)
    PIPELINE2(16, BUF2_BYTES, LOADC, COMPUTEC);
#undef LOADC
#undef COMPUTEC

    __half* Out = (z == 0) ? g_Kh : ((z == 1) ? g_Vh : g_Qh);
#pragma unroll
    for (int mi = 0; mi < 2; mi++)
#pragma unroll
        for (int ni = 0; ni < 8; ni++) {
            int cc = n0 + ni * 8 + (lane & 3) * 2;
#pragma unroll
            for (int half = 0; half < 2; half++) {
                int rr = by * 128 + m0 + mi * 16 + (lane >> 2) + half * 8;
                float d0 = acc[mi][ni][half * 2], d1 = acc[mi][ni][half * 2 + 1];
                int bb = rr >> 10, ss = rr & 1023;
                size_t base = (((size_t)(bx * 8 + bb)) * 1024 + ss) * 128 + cc;
                *(uint32_t*)(Out + base) = pack2h(d0, d1);
            }
        }
}

// ---------------------------------------------------------------------------
// FUSED scores+softmax: one CTA = 32 query rows x 1024 keys. 1-term Qh·Kh.
// S in smem; writes P fp32 (attns output) + Ph fp16 to global.
// ---------------------------------------------------------------------------
__global__ __launch_bounds__(256, 1) void attn_fused_kernel(
    float* __restrict__ attn, const float* __restrict__ qmask,
    const void* __restrict__ mask)
{
    extern __shared__ char smem[];
    uint32_t sb = smem_to_u32(smem);
    float* Ss = (float*)smem;
    int tid = threadIdx.x, lane = tid & 31, w = tid >> 5;
    const int wm = w >> 2;
    const int wn = w & 3;
    int blk = blockIdx.x;
    int y = blockIdx.y;
    int h = y & 7, b = y >> 3;
    int hb = h * 8 + b;
    int q0 = blk * 32;

    const char* Qh = (const char*)(g_Qh + ((size_t)hb * 1024 + q0) * 128);
    const char* Kh = (const char*)(g_Kh + (size_t)hb * 1024 * 128);

#pragma unroll
    for (int i = tid; i < 512; i += 256) {
        int row = i >> 4, ch = i & 15;
        cp16(sb + SM_Q + row * ROWQ + ch * 16, Qh + (size_t)row * 256 + ch * 16);
    }
    CP_COMMIT();

#pragma unroll
    for (int t = 0; t < 2; t++) {
        uint32_t bbuf = sb + SM_B + t * B_BUF;
#pragma unroll
        for (int i = tid; i < 1024; i += 256) {
            int row = i >> 4, ch = i & 15;
            cp16(bbuf + row * ROWQ + ch * 16,
                 Kh + (size_t)t * 64 * 256 + (size_t)row * 256 + ch * 16);
        }
        CP_COMMIT();
    }

    CP_WAIT(2);
    __syncthreads();
    uint32_t ah_reg[8][4];
    {
        uint32_t abase = sb + SM_Q + (uint32_t)(wm * 16 + (lane & 15)) * ROWQ
                         + ((lane >> 4) & 1) * 16;
#pragma unroll
        for (int kk = 0; kk < 8; kk++)
            ldm_x4(ah_reg[kk], abase + kk * 32);
    }

    const int gid = lane >> 2, tig = lane & 3;
    for (int t = 0; t < 16; t++) {
        CP_WAIT(1);
        __syncthreads();
        uint32_t bbuf = sb + SM_B + (t & 1) * B_BUF;
        float acc[2][4];
#pragma unroll
        for (int ni = 0; ni < 2; ni++)
#pragma unroll
            for (int k = 0; k < 4; k++) acc[ni][k] = 0.f;

        uint32_t bbase = bbuf + (uint32_t)(wn * 16 + ((lane >> 4) << 3) + (lane & 7)) * ROWQ
                         + ((lane >> 3) & 1) * 16;
#pragma unroll
        for (int kk = 0; kk < 8; kk++) {
            uint32_t bh[4];
            ldm_x4(bh, bbase + kk * 32);
#pragma unroll
            for (int ni = 0; ni < 2; ni++)
                mma16816(acc[ni], ah_reg[kk], &bh[ni * 2]);
        }
        int col0 = t * 64 + wn * 16;
#pragma unroll
        for (int ni = 0; ni < 2; ni++)
#pragma unroll
            for (int half = 0; half < 2; half++) {
                int row = wm * 16 + gid + half * 8;
                int col = col0 + ni * 8 + tig * 2;
                *(float2*)(Ss + row * S_PITCH + col) =
                    make_float2(acc[ni][half * 2] * SCALE, acc[ni][half * 2 + 1] * SCALE);
            }
        __syncthreads();
        if (t + 2 < 16) {
            uint32_t nbuf = sb + SM_B + (t & 1) * B_BUF;
#pragma unroll
            for (int i = tid; i < 1024; i += 256) {
                int row = i >> 4, ch = i & 15;
                cp16(nbuf + row * ROWQ + ch * 16,
                     Kh + (size_t)(t + 2) * 64 * 256 + (size_t)row * 256 + ch * 16);
            }
        }
        CP_COMMIT();
    }
    __syncthreads();

    const int mode = g_maskmode;
#pragma unroll 1
    for (int j = 0; j < 4; j++) {
        int r = w * 4 + j;
        int q = q0 + r;
        const float* srow = Ss + r * S_PITCH;
        const size_t mrow = ((size_t)b * 1024 + q) * 1024;

        float v[32];
        float mx = -3.4e38f;
#pragma unroll
        for (int c8 = 0; c8 < 8; c8++) {
            int col = c8 * 128 + lane * 4;
            float4 x = *(const float4*)(srow + col);
            int m0i, m1i, m2i, m3i;
            if (mode == 0) {
                int4 mv = *(const int4*)((const int*)mask + mrow + col);
                m0i = mv.x; m1i = mv.y; m2i = mv.z; m3i = mv.w;
            } else if (mode == 1) {
                float4 mv = *(const float4*)((const float*)mask + mrow + col);
                m0i = (mv.x != 0.f); m1i = (mv.y != 0.f); m2i = (mv.z != 0.f); m3i = (mv.w != 0.f);
            } else {
                uchar4 mv = *(const uchar4*)((const unsigned char*)mask + mrow + col);
                m0i = mv.x; m1i = mv.y; m2i = mv.z; m3i = mv.w;
            }
            v[c8*4+0] = m0i ? NEGV : x.x;
            v[c8*4+1] = m1i ? NEGV : x.y;
            v[c8*4+2] = m2i ? NEGV : x.z;
            v[c8*4+3] = m3i ? NEGV : x.w;
            mx = fmaxf(mx, fmaxf(fmaxf(v[c8*4+0], v[c8*4+1]), fmaxf(v[c8*4+2], v[c8*4+3])));
        }
#pragma unroll
        for (int s = 16; s > 0; s >>= 1)
            mx = fmaxf(mx, __shfl_xor_sync(0xFFFFFFFFu, mx, s));

        float sum = 0.f;
#pragma unroll
        for (int i = 0; i < 32; i++) {
            v[i] = expf(v[i] - mx);
            sum += v[i];
        }
#pragma unroll
        for (int s = 16; s > 0; s >>= 1)
            sum += __shfl_xor_sync(0xFFFFFFFFu, sum, s);

        float inv = qmask[b * 1024 + q] / sum;
        float* prow = attn + ((size_t)hb * 1024 + q) * 1024;
        __half* phrow = g_Ph + ((size_t)hb * 1024 + q) * 1024;
#pragma unroll
        for (int c8 = 0; c8 < 8; c8++) {
            int col = c8 * 128 + lane * 4;
            float p0 = v[c8*4+0] * inv, p1 = v[c8*4+1] * inv;
            float p2 = v[c8*4+2] * inv, p3 = v[c8*4+3] * inv;
            *(float4*)(prow + col) = make_float4(p0, p1, p2, p3);
            uint2 hw;
            hw.x = pack2h(p0, p1); hw.y = pack2h(p2, p3);
            *(uint2*)(phrow + col) = hw;
        }
    }
}

// ---------------------------------------------------------------------------
// PV GEMM (HMMA, 1-term fp16, K32, compact smem): O = Ph @ Vt
// ---------------------------------------------------------------------------
__global__ __launch_bounds__(256, 2) void pv_mma_kernel() {
    extern __shared__ char smem[];
    uint32_t sb = smem_to_u32(smem);
    int tid = threadIdx.x, lane = tid & 31, w = tid >> 5;
    int m0 = (w & 3) * 32, n0 = (w >> 2) * 64;
    int bx = blockIdx.x, hb = blockIdx.y;

    const __half* Ah = g_Ph + ((size_t)hb * 1024 + bx * 128) * 1024;
    const __half* Bh = g_Vth + (size_t)hb * DH * SK;

    float acc[2][8][4];
    ACC_ZERO();

#define LOADC(cc, buf) load_chunk1((buf), Ah + (cc)*32, Bh + (cc)*32, 1024, 1024, tid)
#define COMPUTEC(cc, buf) compute_chunk1((buf), lane, m0, n0, acc)
    PIPELINE3(32, BUF1_BYTES, LOADC, COMPUTEC);
#undef LOADC
#undef COMPUTEC

    const int b = hb & 7, h = hb >> 3;
#pragma unroll
    for (int mi = 0; mi < 2; mi++)
#pragma unroll
        for (int ni = 0; ni < 8; ni++) {
            int cc = n0 + ni * 8 + (lane & 3) * 2;
#pragma unroll
            for (int half = 0; half < 2; half++) {
                int q = bx * 128 + m0 + mi * 16 + (lane >> 2) + half * 8;
                float d0 = acc[mi][ni][half * 2], d1 = acc[mi][ni][half * 2 + 1];
                size_t base = ((size_t)b * 1024 + q) * 1024 + h * 128 + cc;
                *(uint32_t*)(g_Oh + base) = pack2h(d0, d1);
            }
        }
}

// ---------------------------------------------------------------------------
// Final GEMM (HMMA, 1-term fp16, K64): X = [dec | O] @ Wf + bf + dec (K=2048)
// ---------------------------------------------------------------------------
__global__ __launch_bounds__(256, 2) void final_mma_kernel(
    const float* __restrict__ dec, const float* __restrict__ bf) {
    extern __shared__ char smem[];
    uint32_t sb = smem_to_u32(smem);
    int tid = threadIdx.x, lane = tid & 31, w = tid >> 5;
    int m0 = (w & 3) * 32, n0 = (w >> 2) * 64;
    int bx = blockIdx.x, by = blockIdx.y;
    const size_t arow0 = (size_t)by * 128;

    const __half* Bh = g_Wft_h + (size_t)bx * 128 * 2048;

    float acc[2][8][4];
    ACC_ZERO();

#define LOADC(cc, buf) do { \
    int _k0 = (cc) * 64; \
    const __half* _a = (_k0 < 1024) ? (g_dech + arow0*1024 + _k0) \
                                    : (g_Oh + arow0*1024 + (_k0 - 1024)); \
    load_chunk64((buf), _a, Bh + _k0, 1024, 2048, tid); \
} while (0)
#define COMPUTEC(cc, buf) compute_chunk64((buf), lane, m0, n0, acc)
    PIPELINE2(32, BUF2_BYTES, LOADC, COMPUTEC);
#undef LOADC
#undef COMPUTEC

#pragma unroll
    for (int mi = 0; mi < 2; mi++)
#pragma unroll
        for (int ni = 0; ni < 8; ni++) {
            int cc = bx * 128 + n0 + ni * 8 + (lane & 3) * 2;
            float2 bv = *(const float2*)(bf + cc);
#pragma unroll
            for (int half = 0; half < 2; half++) {
                int rr = by * 128 + m0 + mi * 16 + (lane >> 2) + half * 8;
                float d0 = acc[mi][ni][half * 2], d1 = acc[mi][ni][half * 2 + 1];
                float2 dv = *(const float2*)(dec + (size_t)rr * 1024 + cc);
                *(float2*)(g_X + (size_t)rr * 1024 + cc) =
                    make_float2(d0 + bv.x + dv.x, d1 + bv.y + dv.y);
            }
        }
}

// ---------------------------------------------------------------------------
// LayerNorm
// ---------------------------------------------------------------------------
__global__ __launch_bounds__(256) void ln_kernel(
    const float* __restrict__ gamma, const float* __restrict__ beta,
    float* __restrict__ out) {
    const int rowid = blockIdx.x;
    const int tid = threadIdx.x;
    const float* rp = g_X + (size_t)rowid * 1024;

    float4 x = *(const float4*)(rp + tid * 4);
    __shared__ float red[256];
    red[tid] = x.x + x.y + x.z + x.w;
    __syncthreads();
#pragma unroll
    for (int s = 128; s > 0; s >>= 1) {
        if (tid < s) red[tid] += red[tid + s];
        __syncthreads();
    }
    float mean = red[0] * (1.0f / 1024.0f);
    __syncthreads();

    float d0 = x.x - mean, d1 = x.y - mean, d2 = x.z - mean, d3 = x.w - mean;
    red[tid] = d0 * d0 + d1 * d1 + d2 * d2 + d3 * d3;
    __syncthreads();
#pragma unroll
    for (int s = 128; s > 0; s >>= 1) {
        if (tid < s) red[tid] += red[tid + s];
        __syncthreads();
    }
    float var = red[0] * (1.0f / 1024.0f);
    float inv = rsqrtf(var + 1e-5f);

    float4 g = *(const float4*)(gamma + tid * 4);
    float4 bt = *(const float4*)(beta + tid * 4);
    float* optr = out + (size_t)rowid * 1024 + tid * 4;
    *(float4*)optr = make_float4(d0 * inv * g.x + bt.x,
                                 d1 * inv * g.y + bt.y,
                                 d2 * inv * g.z + bt.z,
                                 d3 * inv * g.w + bt.w);
}

// ---------------------------------------------------------------------------
extern "C" void kernel_launch(void* const* d_in, const int* in_sizes, int n_in,
                              void* d_out, int out_size) {
    (void)in_sizes; (void)n_in; (void)out_size;
    const float* mem   = (const float*)d_in[0];
    const float* dec   = (const float*)d_in[1];
    const float* qmask = (const float*)d_in[2];
    const float* Wk    = (const float*)d_in[3];
    const float* Wv    = (const float*)d_in[4];
    const float* Wq    = (const float*)d_in[5];
    const float* Wf    = (const float*)d_in[6];
    const float* bf    = (const float*)d_in[7];
    const float* gamma = (const float*)d_in[8];
    const float* beta  = (const float*)d_in[9];
    const void*  mask  = d_in[10];

    float* out  = (float*)d_out;
    float* attn = out + XSIZE;

    cudaFuncSetAttribute(proj_mma_kernel,   cudaFuncAttributeMaxDynamicSharedMemorySize, SMEM2_TOT);
    cudaFuncSetAttribute(attn_fused_kernel, cudaFuncAttributeMaxDynamicSharedMemorySize, SMEM_ATTN);
    cudaFuncSetAttribute(pv_mma_kernel,     cudaFuncAttributeMaxDynamicSharedMemorySize, SMEM1_TOT);
    cudaFuncSetAttribute(final_mma_kernel,  cudaFuncAttributeMaxDynamicSharedMemorySize, SMEM2_TOT);

    detect_mask_kernel<<<1, 32>>>(mask);
    conv_h_kernel<<<8192, 256>>>(mem, 0, XSIZE / 4);
    conv_h_kernel<<<8192, 256>>>(dec, 1, XSIZE / 4);
    convT_kernel<<<dim3(32, 32), dim3(32, 8)>>>(Wk, 0, 1024, 1024);
    convT_kernel<<<dim3(32, 32), dim3(32, 8)>>>(Wv, 1, 1024, 1024);
    convT_kernel<<<dim3(32, 32), dim3(32, 8)>>>(Wq, 2, 1024, 1024);
    convT_kernel<<<dim3(32, 64), dim3(32, 8)>>>(Wf, 3, 2048, 1024);

    proj_mma_kernel<<<dim3(8, 64, 3), 256, SMEM2_TOT>>>();
    transposeV_kernel<<<dim3(4, 32, 64), dim3(32, 8)>>>();
    attn_fused_kernel<<<dim3(32, 64), 256, SMEM_ATTN>>>(attn, qmask, mask);
    pv_mma_kernel<<<dim3(8, 64), 256, SMEM1_TOT>>>();
    final_mma_kernel<<<dim3(8, 64), 256, SMEM2_TOT>>>(dec, bf);
    ln_kernel<<<8192, 256>>>(gamma, beta, out);
}

// round 13
// speedup vs baseline: 1.9203x; 1.1190x over previous
#include <cuda_runtime.h>
#include <cuda_fp16.h>
#include <cstdint>
#include <math.h>

// ---------------------------------------------------------------------------
// Problem constants
// ---------------------------------------------------------------------------
#define NB 8
#define SQ 1024
#define SK 1024
#define DD 1024
#define NH 8
#define DH 128
#define HB (NH*NB)              // 64
#define XSIZE (NB*SQ*DD)        // 8388608
#define NEGV (-4294967295.0f)
#define SCALE 0.0883883476483184405f

// K32-chunk buffers (pv): 128 rows x 32 fp16, pitch 80B
#define ROWB 80
#define OP_BYTES (128*ROWB)       // 10240
#define BUF1_BYTES (2*OP_BYTES)   // 20480  (Ah,Bh)
#define SMEM1_TOT (3*BUF1_BYTES)  // 61440

// K64-chunk 1-term buffers (proj, final): 128 rows x 64 fp16, pitch 144B
#define ROWB2 144
#define OP2_BYTES (128*ROWB2)     // 18432
#define BUF2_BYTES (2*OP2_BYTES)  // 36864  (Ah,Bh)
#define SMEM2_TOT (2*BUF2_BYTES)  // 73728

// attn_fused smem layout: 16 query rows per CTA -> 2 CTA/SM
#define AROWS 16
#define ROWQ 272                  // 256B data + 16B skew
#define S_PITCH 1032              // fp32 words per S row (skewed)
#define SM_Q (AROWS*S_PITCH*4)    // 66048
#define SM_B (SM_Q + AROWS*ROWQ)  // 70400
#define B_BUF (64*ROWQ)           // 17408
#define SMEM_ATTN (SM_B + 2*B_BUF) // 105216

// ---------------------------------------------------------------------------
// Scratch (device globals — referenced ONLY from device code)
// ---------------------------------------------------------------------------
__device__ __half g_memh[NB*SK*DD];
__device__ __half g_dech[NB*SQ*DD];
__device__ __half g_Wkt_h[DD*DD];
__device__ __half g_Wvt_h[DD*DD];
__device__ __half g_Wqt_h[DD*DD];
__device__ __half g_Wft_h[DD*2*DD];
__device__ __half g_Kh[HB*SK*DH];
__device__ __half g_Qh[HB*SQ*DH];
__device__ __half g_Vh[HB*SK*DH];          // [hb][s][d]
__device__ __half g_Vth[HB*DH*SK];         // [hb][d][s]
__device__ __half g_Ph[(size_t)HB*SQ*SK];
__device__ __half g_Oh[NB*SQ*DD];
__device__ float  g_X[NB*SQ*DD];
__device__ int    g_maskmode;

// ---------------------------------------------------------------------------
// Helpers
// ---------------------------------------------------------------------------
__device__ __forceinline__ uint32_t smem_to_u32(const void* p) {
    uint32_t a;
    asm("{ .reg .u64 t; cvta.to.shared.u64 t, %1; cvt.u32.u64 %0, t; }" : "=r"(a) : "l"(p));
    return a;
}

__device__ __forceinline__ void cp16(uint32_t dst, const void* src) {
    asm volatile("cp.async.cg.shared.global [%0], [%1], 16;" :: "r"(dst), "l"(src));
}
#define CP_COMMIT() asm volatile("cp.async.commit_group;" ::: "memory")
#define CP_WAIT(n)  asm volatile("cp.async.wait_group %0;" :: "n"(n) : "memory")

__device__ __forceinline__ void ldm_x4(uint32_t* r, uint32_t addr) {
    asm volatile("ldmatrix.sync.aligned.m8n8.x4.shared.b16 {%0,%1,%2,%3}, [%4];"
        : "=r"(r[0]), "=r"(r[1]), "=r"(r[2]), "=r"(r[3]) : "r"(addr));
}
__device__ __forceinline__ void ldm_x2(uint32_t* r, uint32_t addr) {
    asm volatile("ldmatrix.sync.aligned.m8n8.x2.shared.b16 {%0,%1}, [%2];"
        : "=r"(r[0]), "=r"(r[1]) : "r"(addr));
}

__device__ __forceinline__ void mma16816(float* d, const uint32_t* a, const uint32_t* b) {
    asm volatile("mma.sync.aligned.m16n8k16.row.col.f32.f16.f16.f32 "
        "{%0,%1,%2,%3}, {%4,%5,%6,%7}, {%8,%9}, {%0,%1,%2,%3};"
        : "+f"(d[0]), "+f"(d[1]), "+f"(d[2]), "+f"(d[3])
        : "r"(a[0]), "r"(a[1]), "r"(a[2]), "r"(a[3]), "r"(b[0]), "r"(b[1]));
}

__device__ __forceinline__ uint32_t pack2h(float v0, float v1) {
    __half2 p = __halves2half2(__float2half(v0), __float2half(v1));
    return *reinterpret_cast<uint32_t*>(&p);
}

#define ACC_ZERO() do { \
    _Pragma("unroll") for (int _i = 0; _i < 2; _i++) \
    _Pragma("unroll") for (int _j = 0; _j < 8; _j++) \
    _Pragma("unroll") for (int _k = 0; _k < 4; _k++) acc[_i][_j][_k] = 0.f; \
} while (0)

// ---------------------------------------------------------------------------
// K32-chunk 1-term building blocks (pv)
// ---------------------------------------------------------------------------
__device__ __forceinline__ void load_chunk1(
    uint32_t sbuf, const __half* __restrict__ Ah,
    const __half* __restrict__ Bh, int lda, int ldb, int tid)
{
#pragma unroll
    for (int i = tid; i < 512; i += 256) {
        int row = i >> 2, ch = i & 3;
        uint32_t d = sbuf + row*ROWB + ch*16;
        cp16(d,            (const char*)Ah + (size_t)row * lda * 2 + ch*16);
        cp16(d + OP_BYTES, (const char*)Bh + (size_t)row * ldb * 2 + ch*16);
    }
}

__device__ __forceinline__ void compute_chunk1(uint32_t sbuf, int lane, int m0, int n0,
                                               float acc[2][8][4])
{
#pragma unroll
    for (int kk = 0; kk < 2; kk++) {
        uint32_t ah[2][4];
        int arow = m0 + (lane & 15);
        uint32_t abase = sbuf + kk*32 + ((lane >> 4) & 1)*16;
        ldm_x4(ah[0], abase + arow*ROWB);
        ldm_x4(ah[1], abase + (arow + 16)*ROWB);

        uint32_t bh[4][4];
        int brow = n0 + ((lane >> 4) << 3) + (lane & 7);
        uint32_t bko = ((lane >> 3) & 1) * 16 + kk*32;
#pragma unroll
        for (int nb = 0; nb < 4; nb++)
            ldm_x4(bh[nb], sbuf + OP_BYTES + (brow + nb*16)*ROWB + bko);
#pragma unroll
        for (int mi = 0; mi < 2; mi++)
#pragma unroll
            for (int ni = 0; ni < 8; ni++)
                mma16816(acc[mi][ni], ah[mi], &bh[ni >> 1][(ni & 1) * 2]);
    }
}

#define PIPELINE3(KC, BUFSZ, LOADC, COMPUTEC) do { \
    { LOADC(0, sb + 0*(BUFSZ)); } CP_COMMIT(); \
    { LOADC(1, sb + 1*(BUFSZ)); } CP_COMMIT(); \
    for (int c = 0; c < (KC); c++) { \
        if (c + 2 < (KC)) { LOADC((c + 2), sb + ((c + 2) % 3)*(BUFSZ)); } \
        CP_COMMIT(); \
        CP_WAIT(2); \
        __syncthreads(); \
        { COMPUTEC(c, sb + (c % 3)*(BUFSZ)); } \
        __syncthreads(); \
    } \
} while (0)

// ---------------------------------------------------------------------------
// K64-chunk 1-term building blocks (proj, final)
// ---------------------------------------------------------------------------
__device__ __forceinline__ void load_chunk64(
    uint32_t sbuf, const __half* __restrict__ Ah,
    const __half* __restrict__ Bh, int lda, int ldb, int tid)
{
#pragma unroll
    for (int i = tid; i < 1024; i += 256) {
        int row = i >> 3, ch = i & 7;
        uint32_t d = sbuf + row*ROWB2 + ch*16;
        cp16(d,             (const char*)Ah + (size_t)row * lda * 2 + ch*16);
        cp16(d + OP2_BYTES, (const char*)Bh + (size_t)row * ldb * 2 + ch*16);
    }
}

__device__ __forceinline__ void compute_chunk64(uint32_t sbuf, int lane, int m0, int n0,
                                                float acc[2][8][4])
{
#pragma unroll
    for (int kk = 0; kk < 4; kk++) {
        uint32_t ah[2][4];
        int arow = m0 + (lane & 15);
        uint32_t abase = sbuf + kk*32 + ((lane >> 4) & 1)*16;
        ldm_x4(ah[0], abase + arow*ROWB2);
        ldm_x4(ah[1], abase + (arow + 16)*ROWB2);

        uint32_t bh[4][4];
        int brow = n0 + ((lane >> 4) << 3) + (lane & 7);
        uint32_t bko = ((lane >> 3) & 1) * 16 + kk*32;
#pragma unroll
        for (int nb = 0; nb < 4; nb++)
            ldm_x4(bh[nb], sbuf + OP2_BYTES + (brow + nb*16)*ROWB2 + bko);
#pragma unroll
        for (int mi = 0; mi < 2; mi++)
#pragma unroll
            for (int ni = 0; ni < 8; ni++)
                mma16816(acc[mi][ni], ah[mi], &bh[ni >> 1][(ni & 1) * 2]);
    }
}

#define PIPELINE2(KC, BUFSZ, LOADC, COMPUTEC) do { \
    { LOADC(0, sb); } CP_COMMIT(); \
    for (int c = 0; c < (KC); c++) { \
        if (c + 1 < (KC)) { \
            { LOADC((c + 1), sb + ((c + 1) & 1)*(BUFSZ)); } \
            CP_COMMIT(); \
            CP_WAIT(1); \
        } else CP_WAIT(0); \
        __syncthreads(); \
        { COMPUTEC(c, sb + (c & 1)*(BUFSZ)); } \
        __syncthreads(); \
    } \
} while (0)

// ---------------------------------------------------------------------------
// Mask dtype detection
// ---------------------------------------------------------------------------
__global__ void detect_mask_kernel(const void* __restrict__ mask) {
    int t = threadIdx.x;
    const int* pi = (const int*)mask;
    const float* pf = (const float*)mask;
    bool oki = true, okf = true;
    for (int i = t; i < 256; i += 32) {
        int v = pi[i];
        oki = oki && (v == 0 || v == 1);
        float f = pf[i];
        okf = okf && (f == 0.0f || f == 1.0f);
    }
    oki = __all_sync(0xFFFFFFFFu, oki);
    okf = __all_sync(0xFFFFFFFFu, okf);
    if (t == 0) g_maskmode = oki ? 0 : (okf ? 1 : 2);
}

// ---------------------------------------------------------------------------
// fp32 -> fp16. blockIdx.y: 0=mem, 1=dec
// ---------------------------------------------------------------------------
__global__ void conv_h_kernel(const float* __restrict__ mem,
                              const float* __restrict__ dec, int n4) {
    int which = blockIdx.y;
    const float* __restrict__ src = which ? dec : mem;
    __half* __restrict__ dh = which ? g_dech : g_memh;
    int idx = blockIdx.x * blockDim.x + threadIdx.x;
    if (idx >= n4) return;
    float4 v = ((const float4*)src)[idx];
    uint2 hw;
    hw.x = pack2h(v.x, v.y); hw.y = pack2h(v.z, v.w);
    ((uint2*)dh)[idx] = hw;
}

// ---------------------------------------------------------------------------
// W [1024][1024] fp32 -> Wt [1024][1024] fp16, z selects Wk/Wv/Wq
// ---------------------------------------------------------------------------
__global__ void convT3_kernel(const float* __restrict__ Wk,
                              const float* __restrict__ Wv,
                              const float* __restrict__ Wq) {
    int which = blockIdx.z;
    const float* src = (which == 0) ? Wk : ((which == 1) ? Wv : Wq);
    __half* dh = (which == 0) ? g_Wkt_h : ((which == 1) ? g_Wvt_h : g_Wqt_h);

    __shared__ float t[32][33];
    int n0 = blockIdx.x * 32, k0 = blockIdx.y * 32;
    int tx = threadIdx.x;
    for (int i = threadIdx.y; i < 32; i += 8)
        t[i][tx] = src[(size_t)(k0 + i) * 1024 + n0 + tx];
    __syncthreads();
    for (int i = threadIdx.y; i < 32; i += 8) {
        size_t o = (size_t)(n0 + i) * 1024 + k0 + tx;
        dh[o] = __float2half(t[tx][i]);
    }
}

// Wf [2048][1024] -> Wft [1024][2048]
__global__ void convTWf_kernel(const float* __restrict__ src) {
    __shared__ float t[32][33];
    int n0 = blockIdx.x * 32, k0 = blockIdx.y * 32;
    int tx = threadIdx.x;
    for (int i = threadIdx.y; i < 32; i += 8)
        t[i][tx] = src[(size_t)(k0 + i) * 1024 + n0 + tx];
    __syncthreads();
    for (int i = threadIdx.y; i < 32; i += 8) {
        size_t o = (size_t)(n0 + i) * 2048 + k0 + tx;
        g_Wft_h[o] = __float2half(t[tx][i]);
    }
}

// ---------------------------------------------------------------------------
// V [hb][1024][128] fp16 -> Vt [hb][128][1024] fp16
// ---------------------------------------------------------------------------
__global__ void transposeV_kernel() {
    __shared__ unsigned short t[32][33];
    int hb = blockIdx.z;
    int d0 = blockIdx.x * 32, s0 = blockIdx.y * 32;
    int tx = threadIdx.x;
    const unsigned short* src = (const unsigned short*)g_Vh + (size_t)hb * SK * DH;
    for (int i = threadIdx.y; i < 32; i += 8)
        t[i][tx] = src[(size_t)(s0 + i) * 128 + d0 + tx];
    __syncthreads();
    for (int i = threadIdx.y; i < 32; i += 8) {
        size_t o = (size_t)hb * DH * SK + (size_t)(d0 + i) * 1024 + s0 + tx;
        ((unsigned short*)g_Vth)[o] = t[tx][i];
    }
}

// ---------------------------------------------------------------------------
// Projection GEMM (HMMA, 1-term fp16, K64): z=0 K, z=1 V, z=2 Q. Head-split.
// ---------------------------------------------------------------------------
__global__ __launch_bounds__(256, 2) void proj_mma_kernel() {
    extern __shared__ char smem[];
    uint32_t sb = smem_to_u32(smem);
    int tid = threadIdx.x, lane = tid & 31, w = tid >> 5;
    int m0 = (w & 3) * 32, n0 = (w >> 2) * 64;
    int bx = blockIdx.x, by = blockIdx.y, z = blockIdx.z;

    const __half* Ah = ((z == 2) ? g_dech : g_memh) + (size_t)by * 128 * 1024;
    const __half* Bh = ((z == 0) ? g_Wkt_h : ((z == 1) ? g_Wvt_h : g_Wqt_h))
                       + (size_t)bx * 128 * 1024;

    float acc[2][8][4];
    ACC_ZERO();

#define LOADC(cc, buf) load_chunk64((buf), Ah + (cc)*64, Bh + (cc)*64, 1024, 1024, tid)
#define COMPUTEC(cc, buf) compute_chunk64((buf), lane, m0, n0, acc)
    PIPELINE2(16, BUF2_BYTES, LOADC, COMPUTEC);
#undef LOADC
#undef COMPUTEC

    __half* Out = (z == 0) ? g_Kh : ((z == 1) ? g_Vh : g_Qh);
#pragma unroll
    for (int mi = 0; mi < 2; mi++)
#pragma unroll
        for (int ni = 0; ni < 8; ni++) {
            int cc = n0 + ni * 8 + (lane & 3) * 2;
#pragma unroll
            for (int half = 0; half < 2; half++) {
                int rr = by * 128 + m0 + mi * 16 + (lane >> 2) + half * 8;
                float d0 = acc[mi][ni][half * 2], d1 = acc[mi][ni][half * 2 + 1];
                int bb = rr >> 10, ss = rr & 1023;
                size_t base = (((size_t)(bx * 8 + bb)) * 1024 + ss) * 128 + cc;
                *(uint32_t*)(Out + base) = pack2h(d0, d1);
            }
        }
}

// ---------------------------------------------------------------------------
// FUSED scores+softmax: one CTA = 16 query rows x 1024 keys, 2 CTA/SM.
// All warps share the m16 A fragment; warp w owns n8 slice per 64-key tile.
// ---------------------------------------------------------------------------
__global__ __launch_bounds__(256, 2) void attn_fused_kernel(
    float* __restrict__ attn, const float* __restrict__ qmask,
    const void* __restrict__ mask)
{
    extern __shared__ char smem[];
    uint32_t sb = smem_to_u32(smem);
    float* Ss = (float*)smem;
    int tid = threadIdx.x, lane = tid & 31, w = tid >> 5;
    int blk = blockIdx.x;          // 0..63 row block (16 rows)
    int y = blockIdx.y;            // 0..63 ; b-major for mask L2 reuse
    int h = y & 7, b = y >> 3;
    int hb = h * 8 + b;
    int q0 = blk * AROWS;

    const char* Qh = (const char*)(g_Qh + ((size_t)hb * 1024 + q0) * 128);
    const char* Kh = (const char*)(g_Kh + (size_t)hb * 1024 * 128);

    // ---- load Q (16 rows x 256B): exactly one cp16 per thread ----
    {
        int row = tid >> 4, ch = tid & 15;
        cp16(sb + SM_Q + row * ROWQ + ch * 16, Qh + (size_t)row * 256 + ch * 16);
    }
    CP_COMMIT();

    // ---- preload K tiles 0,1 ----
#pragma unroll
    for (int t = 0; t < 2; t++) {
        uint32_t bbuf = sb + SM_B + t * B_BUF;
#pragma unroll
        for (int i = tid; i < 1024; i += 256) {
            int row = i >> 4, ch = i & 15;
            cp16(bbuf + row * ROWQ + ch * 16,
                 Kh + (size_t)t * 64 * 256 + (size_t)row * 256 + ch * 16);
        }
        CP_COMMIT();
    }

    // ---- Q ready: hoist shared A fragments (all warps identical) ----
    CP_WAIT(2);
    __syncthreads();
    uint32_t ah_reg[8][4];
    {
        uint32_t abase = sb + SM_Q + (uint32_t)(lane & 15) * ROWQ
                         + ((lane >> 4) & 1) * 16;
#pragma unroll
        for (int kk = 0; kk < 8; kk++)
            ldm_x4(ah_reg[kk], abase + kk * 32);
    }

    // ---- stream 16 K tiles of 64 keys; warp w covers keys [w*8, w*8+8) ----
    const int gid = lane >> 2, tig = lane & 3;
    const int n0w = w * 8;
    for (int t = 0; t < 16; t++) {
        CP_WAIT(1);
        __syncthreads();
        uint32_t bbuf = sb + SM_B + (t & 1) * B_BUF;
        float acc[4] = {0.f, 0.f, 0.f, 0.f};
        uint32_t bbase = bbuf + (uint32_t)(n0w + (lane & 7)) * ROWQ
                         + ((lane >> 3) & 1) * 16;
#pragma unroll
        for (int kk = 0; kk < 8; kk++) {
            uint32_t bh[2];
            ldm_x2(bh, bbase + kk * 32);
            mma16816(acc, ah_reg[kk], bh);
        }
        int col0 = t * 64 + n0w + tig * 2;
        *(float2*)(Ss + gid * S_PITCH + col0) =
            make_float2(acc[0] * SCALE, acc[1] * SCALE);
        *(float2*)(Ss + (gid + 8) * S_PITCH + col0) =
            make_float2(acc[2] * SCALE, acc[3] * SCALE);
        __syncthreads();
        if (t + 2 < 16) {
            uint32_t nbuf = sb + SM_B + (t & 1) * B_BUF;
#pragma unroll
            for (int i = tid; i < 1024; i += 256) {
                int row = i >> 4, ch = i & 15;
                cp16(nbuf + row * ROWQ + ch * 16,
                     Kh + (size_t)(t + 2) * 64 * 256 + (size_t)row * 256 + ch * 16);
            }
        }
        CP_COMMIT();
    }
    __syncthreads();

    // ---- softmax: warp w handles rows w*2, w*2+1 ----
    const int mode = g_maskmode;
#pragma unroll 1
    for (int j = 0; j < 2; j++) {
        int r = w * 2 + j;
        int q = q0 + r;
        const float* srow = Ss + r * S_PITCH;
        const size_t mrow = ((size_t)b * 1024 + q) * 1024;

        float v[32];
        float mx = -3.4e38f;
#pragma unroll
        for (int c8 = 0; c8 < 8; c8++) {
            int col = c8 * 128 + lane * 4;
            float4 x = *(const float4*)(srow + col);
            int m0i, m1i, m2i, m3i;
            if (mode == 0) {
                int4 mv = *(const int4*)((const int*)mask + mrow + col);
                m0i = mv.x; m1i = mv.y; m2i = mv.z; m3i = mv.w;
            } else if (mode == 1) {
                float4 mv = *(const float4*)((const float*)mask + mrow + col);
                m0i = (mv.x != 0.f); m1i = (mv.y != 0.f); m2i = (mv.z != 0.f); m3i = (mv.w != 0.f);
            } else {
                uchar4 mv = *(const uchar4*)((const unsigned char*)mask + mrow + col);
                m0i = mv.x; m1i = mv.y; m2i = mv.z; m3i = mv.w;
            }
            v[c8*4+0] = m0i ? NEGV : x.x;
            v[c8*4+1] = m1i ? NEGV : x.y;
            v[c8*4+2] = m2i ? NEGV : x.z;
            v[c8*4+3] = m3i ? NEGV : x.w;
            mx = fmaxf(mx, fmaxf(fmaxf(v[c8*4+0], v[c8*4+1]), fmaxf(v[c8*4+2], v[c8*4+3])));
        }
#pragma unroll
        for (int s = 16; s > 0; s >>= 1)
            mx = fmaxf(mx, __shfl_xor_sync(0xFFFFFFFFu, mx, s));

        float sum = 0.f;
#pragma unroll
        for (int i = 0; i < 32; i++) {
            v[i] = __expf(v[i] - mx);
            sum += v[i];
        }
#pragma unroll
        for (int s = 16; s > 0; s >>= 1)
            sum += __shfl_xor_sync(0xFFFFFFFFu, sum, s);

        float inv = qmask[b * 1024 + q] / sum;
        float* prow = attn + ((size_t)hb * 1024 + q) * 1024;
        __half* phrow = g_Ph + ((size_t)hb * 1024 + q) * 1024;
#pragma unroll
        for (int c8 = 0; c8 < 8; c8++) {
            int col = c8 * 128 + lane * 4;
            float p0 = v[c8*4+0] * inv, p1 = v[c8*4+1] * inv;
            float p2 = v[c8*4+2] * inv, p3 = v[c8*4+3] * inv;
            *(float4*)(prow + col) = make_float4(p0, p1, p2, p3);
            uint2 hw;
            hw.x = pack2h(p0, p1); hw.y = pack2h(p2, p3);
            *(uint2*)(phrow + col) = hw;
        }
    }
}

// ---------------------------------------------------------------------------
// PV GEMM (HMMA, 1-term fp16, K32, compact smem): O = Ph @ Vt
// ---------------------------------------------------------------------------
__global__ __launch_bounds__(256, 2) void pv_mma_kernel() {
    extern __shared__ char smem[];
    uint32_t sb = smem_to_u32(smem);
    int tid = threadIdx.x, lane = tid & 31, w = tid >> 5;
    int m0 = (w & 3) * 32, n0 = (w >> 2) * 64;
    int bx = blockIdx.x, hb = blockIdx.y;

    const __half* Ah = g_Ph + ((size_t)hb * 1024 + bx * 128) * 1024;
    const __half* Bh = g_Vth + (size_t)hb * DH * SK;

    float acc[2][8][4];
    ACC_ZERO();

#define LOADC(cc, buf) load_chunk1((buf), Ah + (cc)*32, Bh + (cc)*32, 1024, 1024, tid)
#define COMPUTEC(cc, buf) compute_chunk1((buf), lane, m0, n0, acc)
    PIPELINE3(32, BUF1_BYTES, LOADC, COMPUTEC);
#undef LOADC
#undef COMPUTEC

    const int b = hb & 7, h = hb >> 3;
#pragma unroll
    for (int mi = 0; mi < 2; mi++)
#pragma unroll
        for (int ni = 0; ni < 8; ni++) {
            int cc = n0 + ni * 8 + (lane & 3) * 2;
#pragma unroll
            for (int half = 0; half < 2; half++) {
                int q = bx * 128 + m0 + mi * 16 + (lane >> 2) + half * 8;
                float d0 = acc[mi][ni][half * 2], d1 = acc[mi][ni][half * 2 + 1];
                size_t base = ((size_t)b * 1024 + q) * 1024 + h * 128 + cc;
                *(uint32_t*)(g_Oh + base) = pack2h(d0, d1);
            }
        }
}

// ---------------------------------------------------------------------------
// Final GEMM (HMMA, 1-term fp16, K64): X = [dec | O] @ Wf + bf + dec (K=2048)
// ---------------------------------------------------------------------------
__global__ __launch_bounds__(256, 2) void final_mma_kernel(
    const float* __restrict__ dec, const float* __restrict__ bf) {
    extern __shared__ char smem[];
    uint32_t sb = smem_to_u32(smem);
    int tid = threadIdx.x, lane = tid & 31, w = tid >> 5;
    int m0 = (w & 3) * 32, n0 = (w >> 2) * 64;
    int bx = blockIdx.x, by = blockIdx.y;
    const size_t arow0 = (size_t)by * 128;

    const __half* Bh = g_Wft_h + (size_t)bx * 128 * 2048;

    float acc[2][8][4];
    ACC_ZERO();

#define LOADC(cc, buf) do { \
    int _k0 = (cc) * 64; \
    const __half* _a = (_k0 < 1024) ? (g_dech + arow0*1024 + _k0) \
                                    : (g_Oh + arow0*1024 + (_k0 - 1024)); \
    load_chunk64((buf), _a, Bh + _k0, 1024, 2048, tid); \
} while (0)
#define COMPUTEC(cc, buf) compute_chunk64((buf), lane, m0, n0, acc)
    PIPELINE2(32, BUF2_BYTES, LOADC, COMPUTEC);
#undef LOADC
#undef COMPUTEC

#pragma unroll
    for (int mi = 0; mi < 2; mi++)
#pragma unroll
        for (int ni = 0; ni < 8; ni++) {
            int cc = bx * 128 + n0 + ni * 8 + (lane & 3) * 2;
            float2 bv = *(const float2*)(bf + cc);
#pragma unroll
            for (int half = 0; half < 2; half++) {
                int rr = by * 128 + m0 + mi * 16 + (lane >> 2) + half * 8;
                float d0 = acc[mi][ni][half * 2], d1 = acc[mi][ni][half * 2 + 1];
                float2 dv = *(const float2*)(dec + (size_t)rr * 1024 + cc);
                *(float2*)(g_X + (size_t)rr * 1024 + cc) =
                    make_float2(d0 + bv.x + dv.x, d1 + bv.y + dv.y);
            }
        }
}

// ---------------------------------------------------------------------------
// LayerNorm
// ---------------------------------------------------------------------------
__global__ __launch_bounds__(256) void ln_kernel(
    const float* __restrict__ gamma, const float* __restrict__ beta,
    float* __restrict__ out) {
    const int rowid = blockIdx.x;
    const int tid = threadIdx.x;
    const float* rp = g_X + (size_t)rowid * 1024;

    float4 x = *(const float4*)(rp + tid * 4);
    __shared__ float red[256];
    red[tid] = x.x + x.y + x.z + x.w;
    __syncthreads();
#pragma unroll
    for (int s = 128; s > 0; s >>= 1) {
        if (tid < s) red[tid] += red[tid + s];
        __syncthreads();
    }
    float mean = red[0] * (1.0f / 1024.0f);
    __syncthreads();

    float d0 = x.x - mean, d1 = x.y - mean, d2 = x.z - mean, d3 = x.w - mean;
    red[tid] = d0 * d0 + d1 * d1 + d2 * d2 + d3 * d3;
    __syncthreads();
#pragma unroll
    for (int s = 128; s > 0; s >>= 1) {
        if (tid < s) red[tid] += red[tid + s];
        __syncthreads();
    }
    float var = red[0] * (1.0f / 1024.0f);
    float inv = rsqrtf(var + 1e-5f);

    float4 g = *(const float4*)(gamma + tid * 4);
    float4 bt = *(const float4*)(beta + tid * 4);
    float* optr = out + (size_t)rowid * 1024 + tid * 4;
    *(float4*)optr = make_float4(d0 * inv * g.x + bt.x,
                                 d1 * inv * g.y + bt.y,
                                 d2 * inv * g.z + bt.z,
                                 d3 * inv * g.w + bt.w);
}

// ---------------------------------------------------------------------------
extern "C" void kernel_launch(void* const* d_in, const int* in_sizes, int n_in,
                              void* d_out, int out_size) {
    (void)in_sizes; (void)n_in; (void)out_size;
    const float* mem   = (const float*)d_in[0];
    const float* dec   = (const float*)d_in[1];
    const float* qmask = (const float*)d_in[2];
    const float* Wk    = (const float*)d_in[3];
    const float* Wv    = (const float*)d_in[4];
    const float* Wq    = (const float*)d_in[5];
    const float* Wf    = (const float*)d_in[6];
    const float* bf    = (const float*)d_in[7];
    const float* gamma = (const float*)d_in[8];
    const float* beta  = (const float*)d_in[9];
    const void*  mask  = d_in[10];

    float* out  = (float*)d_out;
    float* attn = out + XSIZE;

    cudaFuncSetAttribute(proj_mma_kernel,   cudaFuncAttributeMaxDynamicSharedMemorySize, SMEM2_TOT);
    cudaFuncSetAttribute(attn_fused_kernel, cudaFuncAttributeMaxDynamicSharedMemorySize, SMEM_ATTN);
    cudaFuncSetAttribute(pv_mma_kernel,     cudaFuncAttributeMaxDynamicSharedMemorySize, SMEM1_TOT);
    cudaFuncSetAttribute(final_mma_kernel,  cudaFuncAttributeMaxDynamicSharedMemorySize, SMEM2_TOT);

    detect_mask_kernel<<<1, 32>>>(mask);
    conv_h_kernel<<<dim3(8192, 2), 256>>>(mem, dec, XSIZE / 4);
    convT3_kernel<<<dim3(32, 32, 3), dim3(32, 8)>>>(Wk, Wv, Wq);
    convTWf_kernel<<<dim3(32, 64), dim3(32, 8)>>>(Wf);

    proj_mma_kernel<<<dim3(8, 64, 3), 256, SMEM2_TOT>>>();
    transposeV_kernel<<<dim3(4, 32, 64), dim3(32, 8)>>>();
    attn_fused_kernel<<<dim3(64, 64), 256, SMEM_ATTN>>>(attn, qmask, mask);
    pv_mma_kernel<<<dim3(8, 64), 256, SMEM1_TOT>>>();
    final_mma_kernel<<<dim3(8, 64), 256, SMEM2_TOT>>>(dec, bf);
    ln_kernel<<<8192, 256>>>(gamma, beta, out);
}